// round 1
// baseline (speedup 1.0000x reference)
#include <cuda_runtime.h>

// ---------------------------------------------------------------------------
// DilatedMHCABlock: out = Proj_o( DilatedAttn( x@Wq+bq, x@Wk+bk, x@Wv+bv ) )
// B=4, N=2048, D=1024, H=16, DH=64, k=8, dilation=2 (window = +/-16, stride 2)
// Round 1: full-fp32 correctness baseline, GEMMs use packed f32x2 FMA.
// ---------------------------------------------------------------------------

namespace {
constexpr int Bc = 4, Nc = 2048, Dc = 1024, Hc = 16, DHc = 64;
constexpr int KWIN = 8, DIL = 2, WIN = KWIN * DIL;   // 16
constexpr int Mc = Bc * Nc;                          // 8192 tokens
constexpr int NKEYS = 2 * KWIN + 1;                  // 17
}

// scratch (device globals: allocation-free per harness rules)
__device__ float g_Q[Mc * Dc];
__device__ float g_K[Mc * Dc];
__device__ float g_V[Mc * Dc];
__device__ float g_A[Mc * Dc];

// ---------------------------------------------------------------------------
// GEMM: C[M,N] = A[M,K] @ W[K,N] + bias[N], all row-major fp32.
// 128x128x16 tile, 256 threads, 8x8 micro-tile, double-buffered smem,
// accumulators packed 2-wide along N for fma.rn.f32x2.
// ---------------------------------------------------------------------------

#define FMA2(c, a, b) asm("fma.rn.f32x2 %0, %1, %2, %0;" : "+l"(c) : "l"(a), "l"(b))

__device__ __forceinline__ unsigned long long pack2(float x) {
    unsigned long long r;
    unsigned int u = __float_as_uint(x);
    asm("mov.b64 %0, {%1, %2};" : "=l"(r) : "r"(u), "r"(u));
    return r;
}

constexpr int BM = 128, BN = 128, BK = 16;

__global__ __launch_bounds__(256) void gemm_bias_kernel(
    const float* __restrict__ A, const float* __restrict__ W,
    const float* __restrict__ bias, float* __restrict__ C,
    int Mt, int Nt, int Kt)
{
    __shared__ float As[2][BK][BM + 4];
    __shared__ float Bs[2][BK][BN + 4];

    const int tid = threadIdx.x;
    const int m0 = blockIdx.y * BM;
    const int n0 = blockIdx.x * BN;
    const int ty = tid >> 4, tx = tid & 15;

    const int arow = tid >> 2;   // 0..63  (A tile row / 2 halves)
    const int ac4  = tid & 3;    // which float4 along K
    const int brow = tid >> 5;   // 0..7   (B tile k-row / 2 halves)
    const int bc4  = tid & 31;   // which float4 along N

    const float* Ap = A + m0 * Kt;
    const float* Wp = W + n0;

    unsigned long long acc[8][4];
    #pragma unroll
    for (int i = 0; i < 8; ++i)
        #pragma unroll
        for (int j = 0; j < 4; ++j) acc[i][j] = 0ull;

    const int T = Kt / BK;

    // preload tile 0
    #pragma unroll
    for (int p = 0; p < 2; ++p) {
        float4 av = *(const float4*)(Ap + (arow + p * 64) * Kt + ac4 * 4);
        As[0][ac4 * 4 + 0][arow + p * 64] = av.x;
        As[0][ac4 * 4 + 1][arow + p * 64] = av.y;
        As[0][ac4 * 4 + 2][arow + p * 64] = av.z;
        As[0][ac4 * 4 + 3][arow + p * 64] = av.w;
        float4 bv = *(const float4*)(Wp + (brow + p * 8) * Nt + bc4 * 4);
        *(float4*)&Bs[0][brow + p * 8][bc4 * 4] = bv;
    }
    __syncthreads();

    for (int kt = 0; kt < T; ++kt) {
        const int s = kt & 1;
        float4 ra[2], rb[2];
        const bool pref = (kt + 1 < T);
        if (pref) {
            const int k0 = (kt + 1) * BK;
            #pragma unroll
            for (int p = 0; p < 2; ++p) {
                ra[p] = *(const float4*)(Ap + (arow + p * 64) * Kt + k0 + ac4 * 4);
                rb[p] = *(const float4*)(Wp + (k0 + brow + p * 8) * Nt + bc4 * 4);
            }
        }

        #pragma unroll
        for (int kk = 0; kk < BK; ++kk) {
            float4 a0 = *(const float4*)&As[s][kk][ty * 8];
            float4 a1 = *(const float4*)&As[s][kk][ty * 8 + 4];
            ulonglong2 b0 = *(const ulonglong2*)&Bs[s][kk][tx * 8];
            ulonglong2 b1 = *(const ulonglong2*)&Bs[s][kk][tx * 8 + 4];
            unsigned long long a2[8];
            a2[0] = pack2(a0.x); a2[1] = pack2(a0.y);
            a2[2] = pack2(a0.z); a2[3] = pack2(a0.w);
            a2[4] = pack2(a1.x); a2[5] = pack2(a1.y);
            a2[6] = pack2(a1.z); a2[7] = pack2(a1.w);
            unsigned long long bv[4] = { b0.x, b0.y, b1.x, b1.y };
            #pragma unroll
            for (int i = 0; i < 8; ++i)
                #pragma unroll
                for (int j = 0; j < 4; ++j)
                    FMA2(acc[i][j], a2[i], bv[j]);
        }

        if (pref) {
            const int ns = s ^ 1;
            #pragma unroll
            for (int p = 0; p < 2; ++p) {
                As[ns][ac4 * 4 + 0][arow + p * 64] = ra[p].x;
                As[ns][ac4 * 4 + 1][arow + p * 64] = ra[p].y;
                As[ns][ac4 * 4 + 2][arow + p * 64] = ra[p].z;
                As[ns][ac4 * 4 + 3][arow + p * 64] = ra[p].w;
                *(float4*)&Bs[ns][brow + p * 8][bc4 * 4] = rb[p];
            }
        }
        __syncthreads();
    }

    // epilogue: unpack + bias + vector store
    float4 bias0 = *(const float4*)(bias + n0 + tx * 8);
    float4 bias1 = *(const float4*)(bias + n0 + tx * 8 + 4);
    float bb[8] = { bias0.x, bias0.y, bias0.z, bias0.w,
                    bias1.x, bias1.y, bias1.z, bias1.w };
    #pragma unroll
    for (int i = 0; i < 8; ++i) {
        float out[8];
        #pragma unroll
        for (int j = 0; j < 4; ++j) {
            unsigned int lo, hi;
            asm("mov.b64 {%0, %1}, %2;" : "=r"(lo), "=r"(hi) : "l"(acc[i][j]));
            out[2 * j]     = __uint_as_float(lo) + bb[2 * j];
            out[2 * j + 1] = __uint_as_float(hi) + bb[2 * j + 1];
        }
        float* cp = C + (m0 + ty * 8 + i) * Nt + n0 + tx * 8;
        *(float4*)cp       = make_float4(out[0], out[1], out[2], out[3]);
        *(float4*)(cp + 4) = make_float4(out[4], out[5], out[6], out[7]);
    }
}

// ---------------------------------------------------------------------------
// Dilated attention. Block = one (b, h, 64-query tile). K/V window (96 rows
// x 64 dims) staged in smem. Warp per query (8 queries/warp), lane holds
// 2 head-dims; scores via butterfly reduce; masked offsets get -1e30 -> p=0.
// ---------------------------------------------------------------------------

constexpr int QB = 64;
constexpr int KROWS = QB + 2 * WIN;   // 96

__global__ __launch_bounds__(256) void dil_attn_kernel(
    const float* __restrict__ Q, const float* __restrict__ K,
    const float* __restrict__ V, float* __restrict__ O)
{
    __shared__ float Ks[KROWS][DHc];
    __shared__ float Vs[KROWS][DHc];

    const int tid = threadIdx.x;
    const int qb = blockIdx.x & 31;          // N/QB = 32
    const int h  = (blockIdx.x >> 5) & 15;
    const int b  = blockIdx.x >> 9;
    const int q0 = qb * QB;

    // stage K,V window: rows [q0-16, q0+80)
    for (int idx = tid; idx < KROWS * 32; idx += 256) {
        const int r  = idx >> 5;
        const int c2 = idx & 31;
        const int j  = q0 - WIN + r;
        float2 kv = make_float2(0.f, 0.f), vv = make_float2(0.f, 0.f);
        if (j >= 0 && j < Nc) {
            const int off = (b * Nc + j) * Dc + h * DHc + c2 * 2;
            kv = *(const float2*)(K + off);
            vv = *(const float2*)(V + off);
        }
        *(float2*)&Ks[r][c2 * 2] = kv;
        *(float2*)&Vs[r][c2 * 2] = vv;
    }
    __syncthreads();

    const int w = tid >> 5, lane = tid & 31;
    for (int qi = 0; qi < 8; ++qi) {
        const int i = q0 + w * 8 + qi;
        const int qoff = (b * Nc + i) * Dc + h * DHc + lane * 2;
        const float2 q = *(const float2*)(Q + qoff);

        float s[NKEYS];
        #pragma unroll
        for (int m = 0; m < NKEYS; ++m) {
            const int j = i + (m - KWIN) * DIL;
            const int r = j - q0 + WIN;           // always in [0, 96)
            const float2 kk = *(const float2*)&Ks[r][lane * 2];
            float p = q.x * kk.x + q.y * kk.y;
            #pragma unroll
            for (int off = 16; off > 0; off >>= 1)
                p += __shfl_xor_sync(0xffffffffu, p, off);
            s[m] = (j >= 0 && j < Nc) ? p * 0.125f : -1e30f;
        }

        float mx = -1e30f;
        #pragma unroll
        for (int m = 0; m < NKEYS; ++m) mx = fmaxf(mx, s[m]);
        float den = 0.f;
        #pragma unroll
        for (int m = 0; m < NKEYS; ++m) { s[m] = __expf(s[m] - mx); den += s[m]; }
        const float inv = 1.f / den;

        float ox = 0.f, oy = 0.f;
        #pragma unroll
        for (int m = 0; m < NKEYS; ++m) {
            const int j = i + (m - KWIN) * DIL;
            const int r = j - q0 + WIN;
            const float2 vv = *(const float2*)&Vs[r][lane * 2];  // masked rows: weight 0
            ox += s[m] * vv.x;
            oy += s[m] * vv.y;
        }
        *(float2*)(O + qoff) = make_float2(ox * inv, oy * inv);
    }
}

// ---------------------------------------------------------------------------
// launch
// ---------------------------------------------------------------------------

extern "C" void kernel_launch(void* const* d_in, const int* in_sizes, int n_in,
                              void* d_out, int out_size) {
    const float* x  = (const float*)d_in[0];
    const float* Wq = (const float*)d_in[1];
    const float* bq = (const float*)d_in[2];
    const float* Wk = (const float*)d_in[3];
    const float* bk = (const float*)d_in[4];
    const float* Wv = (const float*)d_in[5];
    const float* bv = (const float*)d_in[6];
    const float* Wo = (const float*)d_in[7];
    const float* bo = (const float*)d_in[8];
    float* out = (float*)d_out;

    float *Qb, *Kb, *Vb, *Ab;
    cudaGetSymbolAddress((void**)&Qb, g_Q);
    cudaGetSymbolAddress((void**)&Kb, g_K);
    cudaGetSymbolAddress((void**)&Vb, g_V);
    cudaGetSymbolAddress((void**)&Ab, g_A);

    dim3 gg(Dc / BN, Mc / BM);   // (8, 64)
    gemm_bias_kernel<<<gg, 256>>>(x, Wq, bq, Qb, Mc, Dc, Dc);
    gemm_bias_kernel<<<gg, 256>>>(x, Wk, bk, Kb, Mc, Dc, Dc);
    gemm_bias_kernel<<<gg, 256>>>(x, Wv, bv, Vb, Mc, Dc, Dc);

    dil_attn_kernel<<<Bc * Hc * (Nc / QB), 256>>>(Qb, Kb, Vb, Ab);

    gemm_bias_kernel<<<gg, 256>>>(Ab, Wo, bo, out, Mc, Dc, Dc);
}

// round 3
// speedup vs baseline: 3.6968x; 3.6968x over previous
#include <cuda_runtime.h>
#include <cuda_bf16.h>
#include <cstdint>

// ---------------------------------------------------------------------------
// DilatedMHCABlock round 3: GEMMs via warp-level mma.sync bf16 (2-way split,
// fp32 accum). tcgen05 is unusable: harness PTX target is compute_103 (no 'a'
// features), so HMMA/ldmatrix is the highest-rate legal tensor path.
// ---------------------------------------------------------------------------

namespace {
constexpr int Bc = 4, Nc = 2048, Dc = 1024, Hc = 16, DHc = 64;
constexpr int KWIN = 8, DIL = 2, WIN = KWIN * DIL;   // 16
constexpr int Mc = Bc * Nc;                          // 8192
constexpr int NKEYS = 2 * KWIN + 1;                  // 17
}

// ------------------------- device scratch (no allocs) ----------------------
__device__ __align__(1024) __nv_bfloat16 g_xhi[Mc * Dc];
__device__ __align__(1024) __nv_bfloat16 g_xlo[Mc * Dc];
__device__ __align__(1024) __nv_bfloat16 g_wthi[4][Dc * Dc];   // W^T hi [N,K]
__device__ __align__(1024) __nv_bfloat16 g_wtlo[4][Dc * Dc];   // W^T lo
__device__ __align__(1024) float g_Q[Mc * Dc];
__device__ __align__(1024) float g_K[Mc * Dc];
__device__ __align__(1024) float g_V[Mc * Dc];
__device__ __align__(1024) float g_A[Mc * Dc];
__device__ __align__(1024) __nv_bfloat16 g_ahi[Mc * Dc];
__device__ __align__(1024) __nv_bfloat16 g_alo[Mc * Dc];

// ------------------------------ helpers ------------------------------------
__device__ __forceinline__ uint32_t s2u(const void* p) {
    uint32_t a;
    asm("{ .reg .u64 t; cvta.to.shared.u64 t, %1; cvt.u32.u64 %0, t; }"
        : "=r"(a) : "l"(p));
    return a;
}
__device__ __forceinline__ uint32_t swz(uint32_t o) {   // SW128 xor swizzle
    return o ^ ((o >> 3) & 0x70);
}
__device__ __forceinline__ void ldsm4(uint32_t& r0, uint32_t& r1, uint32_t& r2,
                                      uint32_t& r3, uint32_t addr) {
    asm volatile("ldmatrix.sync.aligned.m8n8.x4.shared.b16 {%0,%1,%2,%3}, [%4];"
                 : "=r"(r0), "=r"(r1), "=r"(r2), "=r"(r3) : "r"(addr));
}
__device__ __forceinline__ void mma_bf16(float* d, const uint32_t* a,
                                         const uint32_t* b) {
    asm volatile(
        "mma.sync.aligned.m16n8k16.row.col.f32.bf16.bf16.f32 "
        "{%0,%1,%2,%3}, {%4,%5,%6,%7}, {%8,%9}, {%0,%1,%2,%3};"
        : "+f"(d[0]), "+f"(d[1]), "+f"(d[2]), "+f"(d[3])
        : "r"(a[0]), "r"(a[1]), "r"(a[2]), "r"(a[3]), "r"(b[0]), "r"(b[1]));
}

// ------------------------- conversion kernels ------------------------------
__global__ __launch_bounds__(256) void convert_split(
    const float4* __restrict__ in, __nv_bfloat16* __restrict__ hi,
    __nv_bfloat16* __restrict__ lo, int n4)
{
    int i = blockIdx.x * blockDim.x + threadIdx.x;
    if (i >= n4) return;
    float4 v = in[i];
    __nv_bfloat16 h0 = __float2bfloat16(v.x), h1 = __float2bfloat16(v.y);
    __nv_bfloat16 h2 = __float2bfloat16(v.z), h3 = __float2bfloat16(v.w);
    __nv_bfloat162* hp = (__nv_bfloat162*)hi;
    hp[i * 2]     = __nv_bfloat162(h0, h1);
    hp[i * 2 + 1] = __nv_bfloat162(h2, h3);
    __nv_bfloat162* lp = (__nv_bfloat162*)lo;
    lp[i * 2]     = __nv_bfloat162(__float2bfloat16(v.x - __bfloat162float(h0)),
                                   __float2bfloat16(v.y - __bfloat162float(h1)));
    lp[i * 2 + 1] = __nv_bfloat162(__float2bfloat16(v.z - __bfloat162float(h2)),
                                   __float2bfloat16(v.w - __bfloat162float(h3)));
}

// W [K,N] row-major fp32 -> W^T hi/lo [N,K] bf16
__global__ __launch_bounds__(256) void transpose_split(
    const float* __restrict__ W, __nv_bfloat16* __restrict__ thi,
    __nv_bfloat16* __restrict__ tlo)
{
    __shared__ float t[32][33];
    const int tx = threadIdx.x, ty = threadIdx.y;   // (32, 8)
    const int bx = blockIdx.x, by = blockIdx.y;
    #pragma unroll
    for (int i = 0; i < 4; ++i)
        t[ty + 8 * i][tx] = W[(by * 32 + ty + 8 * i) * Dc + bx * 32 + tx];
    __syncthreads();
    #pragma unroll
    for (int i = 0; i < 4; ++i) {
        float v = t[tx][ty + 8 * i];
        __nv_bfloat16 h = __float2bfloat16(v);
        int n = bx * 32 + ty + 8 * i, kk = by * 32 + tx;
        thi[n * Dc + kk] = h;
        tlo[n * Dc + kk] = __float2bfloat16(v - __bfloat162float(h));
    }
}

// ------------------------- mma.sync split GEMM -----------------------------
// C[128,128] per CTA. A hi/lo [M,K] bf16 K-major; B=W^T hi/lo [N,K] bf16.
// D = Ah@Bh^T + Ah@Bl^T + Al@Bh^T, fp32 accum. 3-stage cp.async pipeline.
namespace {
constexpr int STAGES = 3;
constexpr int STAGE_BYTES = 65536;     // Ah | Al | Bh | Bl, 16KB each
constexpr int SMEM_TOTAL = STAGES * STAGE_BYTES;   // 192 KB
constexpr int NCHUNK = Dc / 64;        // 16
}

__global__ __launch_bounds__(256) void gemm_mma(
    const __nv_bfloat16* __restrict__ Ahi, const __nv_bfloat16* __restrict__ Alo,
    const __nv_bfloat16* __restrict__ Bhi, const __nv_bfloat16* __restrict__ Blo,
    const float* __restrict__ bias, float* __restrict__ C)
{
    extern __shared__ char smem[];
    const uint32_t sb = s2u(smem);
    const int tid = threadIdx.x, wid = tid >> 5, lane = tid & 31;
    const int m0 = blockIdx.y * 128, n0 = blockIdx.x * 128;
    const int wm = (wid & 3) * 32;      // warp m offset in tile
    const int wn = (wid >> 2) * 64;     // warp n offset in tile

    const int col = tid & 7;            // 16B unit within 128B row
    const int r0  = tid >> 3;           // 0..31

    auto load_chunk = [&](int c, int s) {
        const uint32_t base = sb + s * STAGE_BYTES;
        #pragma unroll
        for (int i = 0; i < 4; ++i) {
            const int r = r0 + i * 32;
            const uint32_t so = swz(r * 128 + col * 16);
            const size_t ga = (size_t)(m0 + r) * Dc + c * 64 + col * 8;
            const size_t gb = (size_t)(n0 + r) * Dc + c * 64 + col * 8;
            asm volatile("cp.async.cg.shared.global [%0], [%1], 16;"
                         :: "r"(base + so), "l"(Ahi + ga) : "memory");
            asm volatile("cp.async.cg.shared.global [%0], [%1], 16;"
                         :: "r"(base + 16384 + so), "l"(Alo + ga) : "memory");
            asm volatile("cp.async.cg.shared.global [%0], [%1], 16;"
                         :: "r"(base + 32768 + so), "l"(Bhi + gb) : "memory");
            asm volatile("cp.async.cg.shared.global [%0], [%1], 16;"
                         :: "r"(base + 49152 + so), "l"(Blo + gb) : "memory");
        }
        asm volatile("cp.async.commit_group;" ::: "memory");
    };

    float acc[2][8][4];
    #pragma unroll
    for (int mt = 0; mt < 2; ++mt)
        #pragma unroll
        for (int nt = 0; nt < 8; ++nt)
            #pragma unroll
            for (int j = 0; j < 4; ++j) acc[mt][nt][j] = 0.f;

    load_chunk(0, 0);
    load_chunk(1, 1);
    load_chunk(2, 2);

    // precomputed ldmatrix lane-address offsets (within a tile buffer)
    const int a_row = lane & 15;          // m/n row within 16-row group
    const int a_seg = lane >> 4;          // k 16B segment select (0/1)
    const int b_mi  = lane >> 3;          // matrix index 0..3
    const int b_row = ((b_mi >> 1) << 3) + (lane & 7);
    const int b_seg = b_mi & 1;

    for (int c = 0; c < NCHUNK; ++c) {
        const int s = c % STAGES;
        if (c < NCHUNK - 2)       asm volatile("cp.async.wait_group 2;" ::: "memory");
        else if (c == NCHUNK - 2) asm volatile("cp.async.wait_group 1;" ::: "memory");
        else                      asm volatile("cp.async.wait_group 0;" ::: "memory");
        __syncthreads();

        const uint32_t stage = sb + s * STAGE_BYTES;
        #pragma unroll
        for (int term = 0; term < 3; ++term) {
            const uint32_t sA = stage + (term == 2 ? 16384 : 0);
            const uint32_t sB = stage + 32768 + (term == 1 ? 16384 : 0);
            #pragma unroll
            for (int ks = 0; ks < 4; ++ks) {
                uint32_t a[2][4];
                #pragma unroll
                for (int mt = 0; mt < 2; ++mt) {
                    const uint32_t ad = sA +
                        swz((wm + mt * 16 + a_row) * 128 + ks * 32 + a_seg * 16);
                    ldsm4(a[mt][0], a[mt][1], a[mt][2], a[mt][3], ad);
                }
                uint32_t b[8][2];
                #pragma unroll
                for (int np = 0; np < 4; ++np) {
                    const uint32_t bd = sB +
                        swz((wn + np * 16 + b_row) * 128 + ks * 32 + b_seg * 16);
                    uint32_t t0, t1, t2, t3;
                    ldsm4(t0, t1, t2, t3, bd);
                    b[np * 2][0] = t0;     b[np * 2][1] = t1;
                    b[np * 2 + 1][0] = t2; b[np * 2 + 1][1] = t3;
                }
                #pragma unroll
                for (int mt = 0; mt < 2; ++mt)
                    #pragma unroll
                    for (int nt = 0; nt < 8; ++nt)
                        mma_bf16(acc[mt][nt], a[mt], b[nt]);
            }
        }
        __syncthreads();
        if (c + STAGES < NCHUNK) load_chunk(c + STAGES, s);
    }

    // epilogue: bias + store (thread t covers rows t/4, cols 2*(t%4))
    const int erow = lane >> 2, ecol = (lane & 3) * 2;
    #pragma unroll
    for (int nt = 0; nt < 8; ++nt) {
        const int ncol = n0 + wn + nt * 8 + ecol;
        const float2 bb = *(const float2*)(bias + ncol);
        #pragma unroll
        for (int mt = 0; mt < 2; ++mt) {
            const int row = m0 + wm + mt * 16 + erow;
            float* cp0 = C + (size_t)row * Dc + ncol;
            float* cp1 = C + (size_t)(row + 8) * Dc + ncol;
            *(float2*)cp0 = make_float2(acc[mt][nt][0] + bb.x,
                                        acc[mt][nt][1] + bb.y);
            *(float2*)cp1 = make_float2(acc[mt][nt][2] + bb.x,
                                        acc[mt][nt][3] + bb.y);
        }
    }
}

// ------------------------- dilated attention (unchanged) -------------------
constexpr int QB = 64;
constexpr int KROWS = QB + 2 * WIN;   // 96

__global__ __launch_bounds__(256) void dil_attn_kernel(
    const float* __restrict__ Q, const float* __restrict__ K,
    const float* __restrict__ V, float* __restrict__ O)
{
    __shared__ float Ks[KROWS][DHc];
    __shared__ float Vs[KROWS][DHc];

    const int tid = threadIdx.x;
    const int qb = blockIdx.x & 31;
    const int h  = (blockIdx.x >> 5) & 15;
    const int b  = blockIdx.x >> 9;
    const int q0 = qb * QB;

    for (int idx = tid; idx < KROWS * 32; idx += 256) {
        const int r  = idx >> 5;
        const int c2 = idx & 31;
        const int j  = q0 - WIN + r;
        float2 kv = make_float2(0.f, 0.f), vv = make_float2(0.f, 0.f);
        if (j >= 0 && j < Nc) {
            const int off = (b * Nc + j) * Dc + h * DHc + c2 * 2;
            kv = *(const float2*)(K + off);
            vv = *(const float2*)(V + off);
        }
        *(float2*)&Ks[r][c2 * 2] = kv;
        *(float2*)&Vs[r][c2 * 2] = vv;
    }
    __syncthreads();

    const int w = tid >> 5, lane = tid & 31;
    for (int qi = 0; qi < 8; ++qi) {
        const int i = q0 + w * 8 + qi;
        const int qoff = (b * Nc + i) * Dc + h * DHc + lane * 2;
        const float2 q = *(const float2*)(Q + qoff);

        float s[NKEYS];
        #pragma unroll
        for (int m = 0; m < NKEYS; ++m) {
            const int j = i + (m - KWIN) * DIL;
            const int r = j - q0 + WIN;
            const float2 kk = *(const float2*)&Ks[r][lane * 2];
            float p = q.x * kk.x + q.y * kk.y;
            #pragma unroll
            for (int off = 16; off > 0; off >>= 1)
                p += __shfl_xor_sync(0xffffffffu, p, off);
            s[m] = (j >= 0 && j < Nc) ? p * 0.125f : -1e30f;
        }

        float mx = -1e30f;
        #pragma unroll
        for (int m = 0; m < NKEYS; ++m) mx = fmaxf(mx, s[m]);
        float den = 0.f;
        #pragma unroll
        for (int m = 0; m < NKEYS; ++m) { s[m] = __expf(s[m] - mx); den += s[m]; }
        const float inv = 1.f / den;

        float ox = 0.f, oy = 0.f;
        #pragma unroll
        for (int m = 0; m < NKEYS; ++m) {
            const int j = i + (m - KWIN) * DIL;
            const int r = j - q0 + WIN;
            const float2 vv = *(const float2*)&Vs[r][lane * 2];
            ox += s[m] * vv.x;
            oy += s[m] * vv.y;
        }
        *(float2*)(O + qoff) = make_float2(ox * inv, oy * inv);
    }
}

// --------------------------------- launch ----------------------------------
extern "C" void kernel_launch(void* const* d_in, const int* in_sizes, int n_in,
                              void* d_out, int out_size) {
    const float* x  = (const float*)d_in[0];
    const float* Wq = (const float*)d_in[1];
    const float* bq = (const float*)d_in[2];
    const float* Wk = (const float*)d_in[3];
    const float* bk = (const float*)d_in[4];
    const float* Wv = (const float*)d_in[5];
    const float* bv = (const float*)d_in[6];
    const float* Wo = (const float*)d_in[7];
    const float* bo = (const float*)d_in[8];
    float* out = (float*)d_out;

    __nv_bfloat16 *xhi, *xlo, *whi, *wlo, *ahi, *alo;
    float *Qb, *Kb, *Vb, *Ab;
    cudaGetSymbolAddress((void**)&xhi, g_xhi);
    cudaGetSymbolAddress((void**)&xlo, g_xlo);
    cudaGetSymbolAddress((void**)&whi, g_wthi);
    cudaGetSymbolAddress((void**)&wlo, g_wtlo);
    cudaGetSymbolAddress((void**)&ahi, g_ahi);
    cudaGetSymbolAddress((void**)&alo, g_alo);
    cudaGetSymbolAddress((void**)&Qb, g_Q);
    cudaGetSymbolAddress((void**)&Kb, g_K);
    cudaGetSymbolAddress((void**)&Vb, g_V);
    cudaGetSymbolAddress((void**)&Ab, g_A);

    cudaFuncSetAttribute(gemm_mma, cudaFuncAttributeMaxDynamicSharedMemorySize,
                         SMEM_TOTAL);

    const int n4 = Mc * Dc / 4;
    convert_split<<<n4 / 256, 256>>>((const float4*)x, xhi, xlo, n4);

    dim3 tb(32, 8), tg(32, 32);
    transpose_split<<<tg, tb>>>(Wq, whi + 0 * (size_t)Dc * Dc, wlo + 0 * (size_t)Dc * Dc);
    transpose_split<<<tg, tb>>>(Wk, whi + 1 * (size_t)Dc * Dc, wlo + 1 * (size_t)Dc * Dc);
    transpose_split<<<tg, tb>>>(Wv, whi + 2 * (size_t)Dc * Dc, wlo + 2 * (size_t)Dc * Dc);
    transpose_split<<<tg, tb>>>(Wo, whi + 3 * (size_t)Dc * Dc, wlo + 3 * (size_t)Dc * Dc);

    dim3 gg(Dc / 128, Mc / 128);   // (8, 64)
    gemm_mma<<<gg, 256, SMEM_TOTAL>>>(xhi, xlo, whi + 0 * (size_t)Dc * Dc,
                                      wlo + 0 * (size_t)Dc * Dc, bq, Qb);
    gemm_mma<<<gg, 256, SMEM_TOTAL>>>(xhi, xlo, whi + 1 * (size_t)Dc * Dc,
                                      wlo + 1 * (size_t)Dc * Dc, bk, Kb);
    gemm_mma<<<gg, 256, SMEM_TOTAL>>>(xhi, xlo, whi + 2 * (size_t)Dc * Dc,
                                      wlo + 2 * (size_t)Dc * Dc, bv, Vb);

    dil_attn_kernel<<<Bc * Hc * (Nc / QB), 256>>>(Qb, Kb, Vb, Ab);

    convert_split<<<n4 / 256, 256>>>((const float4*)Ab, ahi, alo, n4);
    gemm_mma<<<gg, 256, SMEM_TOTAL>>>(ahi, alo, whi + 3 * (size_t)Dc * Dc,
                                      wlo + 3 * (size_t)Dc * Dc, bo, out);
}

// round 4
// speedup vs baseline: 3.9478x; 1.0679x over previous
#include <cuda_runtime.h>
#include <cuda_bf16.h>
#include <cstdint>

// ---------------------------------------------------------------------------
// DilatedMHCABlock round 4:
//  - fused QKV HMMA GEMM (z=3 grid, shared A tiles, 12 ldsm/ks fragment reuse)
//  - thread-per-query attention with fused bf16 hi/lo output split
// ---------------------------------------------------------------------------

namespace {
constexpr int Bc = 4, Nc = 2048, Dc = 1024, Hc = 16, DHc = 64;
constexpr int KWIN = 8, DIL = 2, WIN = KWIN * DIL;   // 16
constexpr int Mc = Bc * Nc;                          // 8192
constexpr int NKEYS = 2 * KWIN + 1;                  // 17
}

// ------------------------- device scratch (no allocs) ----------------------
__device__ __align__(1024) __nv_bfloat16 g_xhi[Mc * Dc];
__device__ __align__(1024) __nv_bfloat16 g_xlo[Mc * Dc];
__device__ __align__(1024) __nv_bfloat16 g_wthi[4][Dc * Dc];   // W^T hi [N,K]
__device__ __align__(1024) __nv_bfloat16 g_wtlo[4][Dc * Dc];   // W^T lo
__device__ __align__(1024) float g_Q[Mc * Dc];
__device__ __align__(1024) float g_K[Mc * Dc];
__device__ __align__(1024) float g_V[Mc * Dc];
__device__ __align__(1024) __nv_bfloat16 g_ahi[Mc * Dc];
__device__ __align__(1024) __nv_bfloat16 g_alo[Mc * Dc];

// ------------------------------ helpers ------------------------------------
__device__ __forceinline__ uint32_t s2u(const void* p) {
    uint32_t a;
    asm("{ .reg .u64 t; cvta.to.shared.u64 t, %1; cvt.u32.u64 %0, t; }"
        : "=r"(a) : "l"(p));
    return a;
}
__device__ __forceinline__ uint32_t swz(uint32_t o) {   // SW128 xor swizzle
    return o ^ ((o >> 3) & 0x70);
}
__device__ __forceinline__ void ldsm4(uint32_t& r0, uint32_t& r1, uint32_t& r2,
                                      uint32_t& r3, uint32_t addr) {
    asm volatile("ldmatrix.sync.aligned.m8n8.x4.shared.b16 {%0,%1,%2,%3}, [%4];"
                 : "=r"(r0), "=r"(r1), "=r"(r2), "=r"(r3) : "r"(addr));
}
__device__ __forceinline__ void mma_bf16(float* d, const uint32_t* a,
                                         const uint32_t* b) {
    asm volatile(
        "mma.sync.aligned.m16n8k16.row.col.f32.bf16.bf16.f32 "
        "{%0,%1,%2,%3}, {%4,%5,%6,%7}, {%8,%9}, {%0,%1,%2,%3};"
        : "+f"(d[0]), "+f"(d[1]), "+f"(d[2]), "+f"(d[3])
        : "r"(a[0]), "r"(a[1]), "r"(a[2]), "r"(a[3]), "r"(b[0]), "r"(b[1]));
}

// ------------------------- conversion kernels ------------------------------
__global__ __launch_bounds__(256) void convert_split(
    const float4* __restrict__ in, __nv_bfloat16* __restrict__ hi,
    __nv_bfloat16* __restrict__ lo, int n4)
{
    int i = blockIdx.x * blockDim.x + threadIdx.x;
    if (i >= n4) return;
    float4 v = in[i];
    __nv_bfloat16 h0 = __float2bfloat16(v.x), h1 = __float2bfloat16(v.y);
    __nv_bfloat16 h2 = __float2bfloat16(v.z), h3 = __float2bfloat16(v.w);
    __nv_bfloat162* hp = (__nv_bfloat162*)hi;
    hp[i * 2]     = __nv_bfloat162(h0, h1);
    hp[i * 2 + 1] = __nv_bfloat162(h2, h3);
    __nv_bfloat162* lp = (__nv_bfloat162*)lo;
    lp[i * 2]     = __nv_bfloat162(__float2bfloat16(v.x - __bfloat162float(h0)),
                                   __float2bfloat16(v.y - __bfloat162float(h1)));
    lp[i * 2 + 1] = __nv_bfloat162(__float2bfloat16(v.z - __bfloat162float(h2)),
                                   __float2bfloat16(v.w - __bfloat162float(h3)));
}

// W [K,N] row-major fp32 -> W^T hi/lo [N,K] bf16
__global__ __launch_bounds__(256) void transpose_split(
    const float* __restrict__ W, __nv_bfloat16* __restrict__ thi,
    __nv_bfloat16* __restrict__ tlo)
{
    __shared__ float t[32][33];
    const int tx = threadIdx.x, ty = threadIdx.y;   // (32, 8)
    const int bx = blockIdx.x, by = blockIdx.y;
    #pragma unroll
    for (int i = 0; i < 4; ++i)
        t[ty + 8 * i][tx] = W[(by * 32 + ty + 8 * i) * Dc + bx * 32 + tx];
    __syncthreads();
    #pragma unroll
    for (int i = 0; i < 4; ++i) {
        float v = t[tx][ty + 8 * i];
        __nv_bfloat16 h = __float2bfloat16(v);
        int n = bx * 32 + ty + 8 * i, kk = by * 32 + tx;
        thi[n * Dc + kk] = h;
        tlo[n * Dc + kk] = __float2bfloat16(v - __bfloat162float(h));
    }
}

// ------------------------- mma.sync split GEMM -----------------------------
namespace {
constexpr int STAGES = 3;
constexpr int STAGE_BYTES = 65536;     // Ah | Al | Bh | Bl, 16KB each
constexpr int SMEM_TOTAL = STAGES * STAGE_BYTES;   // 192 KB
constexpr int NCHUNK = Dc / 64;        // 16
}

struct GemmArgs {
    const __nv_bfloat16* Bh[3];
    const __nv_bfloat16* Bl[3];
    const float* bias[3];
    float* C[3];
};

__global__ __launch_bounds__(256) void gemm_mma(
    const __nv_bfloat16* __restrict__ Ahi, const __nv_bfloat16* __restrict__ Alo,
    GemmArgs args)
{
    extern __shared__ char smem[];
    const uint32_t sb = s2u(smem);
    const int tid = threadIdx.x, wid = tid >> 5, lane = tid & 31;
    const int m0 = blockIdx.y * 128, n0 = blockIdx.x * 128;
    const int z = blockIdx.z;
    const __nv_bfloat16* __restrict__ Bhi = args.Bh[z];
    const __nv_bfloat16* __restrict__ Blo = args.Bl[z];
    const float* __restrict__ bias = args.bias[z];
    float* __restrict__ C = args.C[z];

    const int wm = (wid & 3) * 32;      // warp m offset in tile
    const int wn = (wid >> 2) * 64;     // warp n offset in tile

    const int col = tid & 7;            // 16B unit within 128B row
    const int r0  = tid >> 3;           // 0..31

    auto load_chunk = [&](int c, int s) {
        const uint32_t base = sb + s * STAGE_BYTES;
        #pragma unroll
        for (int i = 0; i < 4; ++i) {
            const int r = r0 + i * 32;
            const uint32_t so = swz(r * 128 + col * 16);
            const size_t ga = (size_t)(m0 + r) * Dc + c * 64 + col * 8;
            const size_t gb = (size_t)(n0 + r) * Dc + c * 64 + col * 8;
            asm volatile("cp.async.cg.shared.global [%0], [%1], 16;"
                         :: "r"(base + so), "l"(Ahi + ga) : "memory");
            asm volatile("cp.async.cg.shared.global [%0], [%1], 16;"
                         :: "r"(base + 16384 + so), "l"(Alo + ga) : "memory");
            asm volatile("cp.async.cg.shared.global [%0], [%1], 16;"
                         :: "r"(base + 32768 + so), "l"(Bhi + gb) : "memory");
            asm volatile("cp.async.cg.shared.global [%0], [%1], 16;"
                         :: "r"(base + 49152 + so), "l"(Blo + gb) : "memory");
        }
        asm volatile("cp.async.commit_group;" ::: "memory");
    };

    float acc[2][8][4];
    #pragma unroll
    for (int mt = 0; mt < 2; ++mt)
        #pragma unroll
        for (int nt = 0; nt < 8; ++nt)
            #pragma unroll
            for (int j = 0; j < 4; ++j) acc[mt][nt][j] = 0.f;

    load_chunk(0, 0);
    load_chunk(1, 1);
    load_chunk(2, 2);

    const int a_row = lane & 15;
    const int a_seg = lane >> 4;
    const int b_mi  = lane >> 3;
    const int b_row = ((b_mi >> 1) << 3) + (lane & 7);
    const int b_seg = b_mi & 1;

    for (int c = 0; c < NCHUNK; ++c) {
        const int s = c % STAGES;
        if (c < NCHUNK - 2)       asm volatile("cp.async.wait_group 2;" ::: "memory");
        else if (c == NCHUNK - 2) asm volatile("cp.async.wait_group 1;" ::: "memory");
        else                      asm volatile("cp.async.wait_group 0;" ::: "memory");
        __syncthreads();

        const uint32_t stage = sb + s * STAGE_BYTES;
        #pragma unroll
        for (int ks = 0; ks < 4; ++ks) {
            // load all fragments once, fire 3 term-MMAs (Ah.Bh, Ah.Bl, Al.Bh)
            uint32_t aH[2][4], aL[2][4];
            #pragma unroll
            for (int mt = 0; mt < 2; ++mt) {
                const uint32_t off =
                    swz((wm + mt * 16 + a_row) * 128 + ks * 32 + a_seg * 16);
                ldsm4(aH[mt][0], aH[mt][1], aH[mt][2], aH[mt][3], stage + off);
                ldsm4(aL[mt][0], aL[mt][1], aL[mt][2], aL[mt][3],
                      stage + 16384 + off);
            }
            uint32_t bH[8][2], bL[8][2];
            #pragma unroll
            for (int np = 0; np < 4; ++np) {
                const uint32_t off =
                    swz((wn + np * 16 + b_row) * 128 + ks * 32 + b_seg * 16);
                uint32_t t0, t1, t2, t3;
                ldsm4(t0, t1, t2, t3, stage + 32768 + off);
                bH[np * 2][0] = t0;     bH[np * 2][1] = t1;
                bH[np * 2 + 1][0] = t2; bH[np * 2 + 1][1] = t3;
                ldsm4(t0, t1, t2, t3, stage + 49152 + off);
                bL[np * 2][0] = t0;     bL[np * 2][1] = t1;
                bL[np * 2 + 1][0] = t2; bL[np * 2 + 1][1] = t3;
            }
            #pragma unroll
            for (int mt = 0; mt < 2; ++mt)
                #pragma unroll
                for (int nt = 0; nt < 8; ++nt) {
                    mma_bf16(acc[mt][nt], aH[mt], bH[nt]);
                    mma_bf16(acc[mt][nt], aH[mt], bL[nt]);
                    mma_bf16(acc[mt][nt], aL[mt], bH[nt]);
                }
        }
        __syncthreads();
        if (c + STAGES < NCHUNK) load_chunk(c + STAGES, s);
    }

    const int erow = lane >> 2, ecol = (lane & 3) * 2;
    #pragma unroll
    for (int nt = 0; nt < 8; ++nt) {
        const int ncol = n0 + wn + nt * 8 + ecol;
        const float2 bb = *(const float2*)(bias + ncol);
        #pragma unroll
        for (int mt = 0; mt < 2; ++mt) {
            const int row = m0 + wm + mt * 16 + erow;
            float* cp0 = C + (size_t)row * Dc + ncol;
            float* cp1 = C + (size_t)(row + 8) * Dc + ncol;
            *(float2*)cp0 = make_float2(acc[mt][nt][0] + bb.x,
                                        acc[mt][nt][1] + bb.y);
            *(float2*)cp1 = make_float2(acc[mt][nt][2] + bb.x,
                                        acc[mt][nt][3] + bb.y);
        }
    }
}

// ------------------------- attention: thread-per-query ---------------------
// Block = (b, h, 128-query tile), 128 threads, thread t -> query q0+t.
// K/V window (160 rows x 64) in smem (pad 66 -> max 2-way LDS.64 conflicts).
// Output written directly as bf16 hi/lo split (feeds O-projection).
namespace {
constexpr int QT = 128;
constexpr int RW = QT + 2 * WIN;   // 160
constexpr int APAD = 66;
constexpr int ASMEM = 2 * RW * APAD * 4;   // 84480 B
}

__global__ __launch_bounds__(128) void dil_attn2(
    const float* __restrict__ Q, const float* __restrict__ K,
    const float* __restrict__ V, __nv_bfloat16* __restrict__ Ohi,
    __nv_bfloat16* __restrict__ Olo)
{
    extern __shared__ float sm[];
    float* Ks = sm;                    // [RW][APAD]
    float* Vs = sm + RW * APAD;

    const int tid = threadIdx.x;
    const int q0 = blockIdx.x * QT;
    const int h  = blockIdx.y;
    const int b  = blockIdx.z;

    // stage K/V rows [q0-16, q0+144)
    for (int idx = tid; idx < RW * 16; idx += 128) {
        const int r  = idx >> 4;
        const int c4 = (idx & 15) * 4;
        const int j  = q0 - WIN + r;
        float4 kv = make_float4(0.f, 0.f, 0.f, 0.f), vv = kv;
        if (j >= 0 && j < Nc) {
            const size_t off = (size_t)(b * Nc + j) * Dc + h * DHc + c4;
            kv = *(const float4*)(K + off);
            vv = *(const float4*)(V + off);
        }
        float* kp = Ks + r * APAD + c4;
        kp[0] = kv.x; kp[1] = kv.y; kp[2] = kv.z; kp[3] = kv.w;
        float* vp = Vs + r * APAD + c4;
        vp[0] = vv.x; vp[1] = vv.y; vp[2] = vv.z; vp[3] = vv.w;
    }
    __syncthreads();

    const int i = q0 + tid;
    const size_t qoff = (size_t)(b * Nc + i) * Dc + h * DHc;

    float qv[DHc];
    #pragma unroll
    for (int d4 = 0; d4 < DHc; d4 += 4) {
        float4 v = *(const float4*)(Q + qoff + d4);
        qv[d4] = v.x; qv[d4 + 1] = v.y; qv[d4 + 2] = v.z; qv[d4 + 3] = v.w;
    }

    float s[NKEYS];
    #pragma unroll
    for (int m = 0; m < NKEYS; ++m) {
        const float* kr = Ks + (tid + 2 * m) * APAD;
        float acc = 0.f;
        #pragma unroll
        for (int d = 0; d < DHc; d += 2) {
            float2 kk = *(const float2*)(kr + d);
            acc += qv[d] * kk.x + qv[d + 1] * kk.y;
        }
        const int j = i + (m - KWIN) * DIL;
        s[m] = (j >= 0 && j < Nc) ? acc * 0.125f : -1e30f;
    }

    float mx = s[0];
    #pragma unroll
    for (int m = 1; m < NKEYS; ++m) mx = fmaxf(mx, s[m]);
    float den = 0.f;
    #pragma unroll
    for (int m = 0; m < NKEYS; ++m) { s[m] = __expf(s[m] - mx); den += s[m]; }
    const float inv = 1.f / den;

    float o[DHc];
    #pragma unroll
    for (int d = 0; d < DHc; ++d) o[d] = 0.f;
    #pragma unroll
    for (int m = 0; m < NKEYS; ++m) {
        const float w = s[m];
        const float* vr = Vs + (tid + 2 * m) * APAD;
        #pragma unroll
        for (int d = 0; d < DHc; d += 2) {
            float2 vv = *(const float2*)(vr + d);
            o[d]     += w * vv.x;
            o[d + 1] += w * vv.y;
        }
    }

    __nv_bfloat162* hp = (__nv_bfloat162*)(Ohi + qoff);
    __nv_bfloat162* lp = (__nv_bfloat162*)(Olo + qoff);
    #pragma unroll
    for (int d = 0; d < DHc; d += 2) {
        float v0 = o[d] * inv, v1 = o[d + 1] * inv;
        __nv_bfloat16 h0 = __float2bfloat16(v0), h1 = __float2bfloat16(v1);
        hp[d / 2] = __nv_bfloat162(h0, h1);
        lp[d / 2] = __nv_bfloat162(__float2bfloat16(v0 - __bfloat162float(h0)),
                                   __float2bfloat16(v1 - __bfloat162float(h1)));
    }
}

// --------------------------------- launch ----------------------------------
extern "C" void kernel_launch(void* const* d_in, const int* in_sizes, int n_in,
                              void* d_out, int out_size) {
    const float* x  = (const float*)d_in[0];
    const float* Wq = (const float*)d_in[1];
    const float* bq = (const float*)d_in[2];
    const float* Wk = (const float*)d_in[3];
    const float* bk = (const float*)d_in[4];
    const float* Wv = (const float*)d_in[5];
    const float* bv = (const float*)d_in[6];
    const float* Wo = (const float*)d_in[7];
    const float* bo = (const float*)d_in[8];
    float* out = (float*)d_out;

    __nv_bfloat16 *xhi, *xlo, *whi, *wlo, *ahi, *alo;
    float *Qb, *Kb, *Vb;
    cudaGetSymbolAddress((void**)&xhi, g_xhi);
    cudaGetSymbolAddress((void**)&xlo, g_xlo);
    cudaGetSymbolAddress((void**)&whi, g_wthi);
    cudaGetSymbolAddress((void**)&wlo, g_wtlo);
    cudaGetSymbolAddress((void**)&ahi, g_ahi);
    cudaGetSymbolAddress((void**)&alo, g_alo);
    cudaGetSymbolAddress((void**)&Qb, g_Q);
    cudaGetSymbolAddress((void**)&Kb, g_K);
    cudaGetSymbolAddress((void**)&Vb, g_V);

    cudaFuncSetAttribute(gemm_mma, cudaFuncAttributeMaxDynamicSharedMemorySize,
                         SMEM_TOTAL);
    cudaFuncSetAttribute(dil_attn2, cudaFuncAttributeMaxDynamicSharedMemorySize,
                         ASMEM);

    const int n4 = Mc * Dc / 4;
    convert_split<<<n4 / 256, 256>>>((const float4*)x, xhi, xlo, n4);

    dim3 tb(32, 8), tg(32, 32);
    transpose_split<<<tg, tb>>>(Wq, whi + 0 * (size_t)Dc * Dc, wlo + 0 * (size_t)Dc * Dc);
    transpose_split<<<tg, tb>>>(Wk, whi + 1 * (size_t)Dc * Dc, wlo + 1 * (size_t)Dc * Dc);
    transpose_split<<<tg, tb>>>(Wv, whi + 2 * (size_t)Dc * Dc, wlo + 2 * (size_t)Dc * Dc);
    transpose_split<<<tg, tb>>>(Wo, whi + 3 * (size_t)Dc * Dc, wlo + 3 * (size_t)Dc * Dc);

    // fused QKV
    GemmArgs qkv;
    qkv.Bh[0] = whi;                       qkv.Bl[0] = wlo;
    qkv.Bh[1] = whi + 1 * (size_t)Dc * Dc; qkv.Bl[1] = wlo + 1 * (size_t)Dc * Dc;
    qkv.Bh[2] = whi + 2 * (size_t)Dc * Dc; qkv.Bl[2] = wlo + 2 * (size_t)Dc * Dc;
    qkv.bias[0] = bq; qkv.bias[1] = bk; qkv.bias[2] = bv;
    qkv.C[0] = Qb; qkv.C[1] = Kb; qkv.C[2] = Vb;
    dim3 gq(Dc / 128, Mc / 128, 3);
    gemm_mma<<<gq, 256, SMEM_TOTAL>>>(xhi, xlo, qkv);

    dim3 ga(Nc / QT, Hc, Bc);   // (16, 16, 4)
    dil_attn2<<<ga, 128, ASMEM>>>(Qb, Kb, Vb, ahi, alo);

    GemmArgs og;
    og.Bh[0] = whi + 3 * (size_t)Dc * Dc; og.Bl[0] = wlo + 3 * (size_t)Dc * Dc;
    og.Bh[1] = og.Bh[0]; og.Bl[1] = og.Bl[0];
    og.Bh[2] = og.Bh[0]; og.Bl[2] = og.Bl[0];
    og.bias[0] = bo; og.bias[1] = bo; og.bias[2] = bo;
    og.C[0] = out; og.C[1] = out; og.C[2] = out;
    dim3 go(Dc / 128, Mc / 128, 1);
    gemm_mma<<<go, 256, SMEM_TOTAL>>>(ahi, alo, og);
}

// round 5
// speedup vs baseline: 5.3496x; 1.3551x over previous
#include <cuda_runtime.h>
#include <cuda_fp16.h>
#include <cstdint>

// ---------------------------------------------------------------------------
// DilatedMHCABlock round 5:
//  - 2-term fp16 GEMM: C = A_fp16 @ (Whi + Wlo)^T, fp32 accum.
//    W pre-scaled by 16 so Wlo stays in fp16 normal range; epilogue /16.
//  - 4-stage cp.async pipeline (48KB/stage), load issued before compute.
//  - x / attention outputs converted to single fp16 (no lo).
//  - all 4 weight transposes fused into one launch.
// ---------------------------------------------------------------------------

namespace {
constexpr int Bc = 4, Nc = 2048, Dc = 1024, Hc = 16, DHc = 64;
constexpr int KWIN = 8, DIL = 2, WIN = KWIN * DIL;   // 16
constexpr int Mc = Bc * Nc;                          // 8192
constexpr int NKEYS = 2 * KWIN + 1;                  // 17
constexpr float WSCALE = 16.0f;
constexpr float INV_WSCALE = 1.0f / 16.0f;
}

// ------------------------- device scratch (no allocs) ----------------------
__device__ __align__(1024) __half g_xh[Mc * Dc];
__device__ __align__(1024) __half g_wthi[4][Dc * Dc];   // (16*W)^T hi [N,K]
__device__ __align__(1024) __half g_wtlo[4][Dc * Dc];   // (16*W)^T lo
__device__ __align__(1024) float g_Q[Mc * Dc];
__device__ __align__(1024) float g_K[Mc * Dc];
__device__ __align__(1024) float g_V[Mc * Dc];
__device__ __align__(1024) __half g_ah[Mc * Dc];

// ------------------------------ helpers ------------------------------------
__device__ __forceinline__ uint32_t s2u(const void* p) {
    uint32_t a;
    asm("{ .reg .u64 t; cvta.to.shared.u64 t, %1; cvt.u32.u64 %0, t; }"
        : "=r"(a) : "l"(p));
    return a;
}
__device__ __forceinline__ uint32_t swz(uint32_t o) {   // SW128 xor swizzle
    return o ^ ((o >> 3) & 0x70);
}
__device__ __forceinline__ void ldsm4(uint32_t& r0, uint32_t& r1, uint32_t& r2,
                                      uint32_t& r3, uint32_t addr) {
    asm volatile("ldmatrix.sync.aligned.m8n8.x4.shared.b16 {%0,%1,%2,%3}, [%4];"
                 : "=r"(r0), "=r"(r1), "=r"(r2), "=r"(r3) : "r"(addr));
}
__device__ __forceinline__ void mma_f16(float* d, const uint32_t* a,
                                        const uint32_t* b) {
    asm volatile(
        "mma.sync.aligned.m16n8k16.row.col.f32.f16.f16.f32 "
        "{%0,%1,%2,%3}, {%4,%5,%6,%7}, {%8,%9}, {%0,%1,%2,%3};"
        : "+f"(d[0]), "+f"(d[1]), "+f"(d[2]), "+f"(d[3])
        : "r"(a[0]), "r"(a[1]), "r"(a[2]), "r"(a[3]), "r"(b[0]), "r"(b[1]));
}

// ------------------------- conversion kernels ------------------------------
__global__ __launch_bounds__(256) void convert_h(
    const float4* __restrict__ in, __half* __restrict__ out, int n4)
{
    int i = blockIdx.x * blockDim.x + threadIdx.x;
    if (i >= n4) return;
    float4 v = in[i];
    __half2* op = (__half2*)out;
    op[i * 2]     = __floats2half2_rn(v.x, v.y);
    op[i * 2 + 1] = __floats2half2_rn(v.z, v.w);
}

// all 4 weights: W [K,N] fp32 -> (16*W)^T hi/lo [N,K] fp16
struct TransArgs {
    const float* W[4];
    __half* hi[4];
    __half* lo[4];
};

__global__ __launch_bounds__(256) void transpose_all(TransArgs args)
{
    __shared__ float t[32][33];
    const int tx = threadIdx.x, ty = threadIdx.y;   // (32, 8)
    const int bx = blockIdx.x, by = blockIdx.y, z = blockIdx.z;
    const float* __restrict__ W = args.W[z];
    __half* __restrict__ thi = args.hi[z];
    __half* __restrict__ tlo = args.lo[z];
    #pragma unroll
    for (int i = 0; i < 4; ++i)
        t[ty + 8 * i][tx] = W[(by * 32 + ty + 8 * i) * Dc + bx * 32 + tx];
    __syncthreads();
    #pragma unroll
    for (int i = 0; i < 4; ++i) {
        float v = t[tx][ty + 8 * i] * WSCALE;
        __half h = __float2half_rn(v);
        int n = bx * 32 + ty + 8 * i, kk = by * 32 + tx;
        thi[n * Dc + kk] = h;
        tlo[n * Dc + kk] = __float2half_rn(v - __half2float(h));
    }
}

// ------------------------- mma.sync 2-term GEMM ----------------------------
namespace {
constexpr int STAGES = 4;
constexpr int STAGE_BYTES = 49152;     // A | Bh | Bl, 16KB each
constexpr int SMEM_TOTAL = STAGES * STAGE_BYTES;   // 192 KB
constexpr int NCHUNK = Dc / 64;        // 16
}

struct GemmArgs {
    const __half* Bh[3];
    const __half* Bl[3];
    const float* bias[3];
    float* C[3];
};

__global__ __launch_bounds__(256) void gemm_mma(
    const __half* __restrict__ Ah, GemmArgs args)
{
    extern __shared__ char smem[];
    const uint32_t sb = s2u(smem);
    const int tid = threadIdx.x, wid = tid >> 5, lane = tid & 31;
    const int m0 = blockIdx.y * 128, n0 = blockIdx.x * 128;
    const int z = blockIdx.z;
    const __half* __restrict__ Bhi = args.Bh[z];
    const __half* __restrict__ Blo = args.Bl[z];
    const float* __restrict__ bias = args.bias[z];
    float* __restrict__ C = args.C[z];

    const int wm = (wid & 3) * 32;      // warp m offset
    const int wn = (wid >> 2) * 64;     // warp n offset

    const int col = tid & 7;            // 16B unit within 128B row
    const int r0  = tid >> 3;           // 0..31

    auto load_chunk = [&](int c, int s) {
        const uint32_t base = sb + s * STAGE_BYTES;
        #pragma unroll
        for (int i = 0; i < 4; ++i) {
            const int r = r0 + i * 32;
            const uint32_t so = swz(r * 128 + col * 16);
            const size_t ga = (size_t)(m0 + r) * Dc + c * 64 + col * 8;
            const size_t gb = (size_t)(n0 + r) * Dc + c * 64 + col * 8;
            asm volatile("cp.async.cg.shared.global [%0], [%1], 16;"
                         :: "r"(base + so), "l"(Ah + ga) : "memory");
            asm volatile("cp.async.cg.shared.global [%0], [%1], 16;"
                         :: "r"(base + 16384 + so), "l"(Bhi + gb) : "memory");
            asm volatile("cp.async.cg.shared.global [%0], [%1], 16;"
                         :: "r"(base + 32768 + so), "l"(Blo + gb) : "memory");
        }
        asm volatile("cp.async.commit_group;" ::: "memory");
    };

    float acc[2][8][4];
    #pragma unroll
    for (int mt = 0; mt < 2; ++mt)
        #pragma unroll
        for (int nt = 0; nt < 8; ++nt)
            #pragma unroll
            for (int j = 0; j < 4; ++j) acc[mt][nt][j] = 0.f;

    load_chunk(0, 0);
    load_chunk(1, 1);
    load_chunk(2, 2);

    const int a_row = lane & 15;
    const int a_seg = lane >> 4;
    const int b_mi  = lane >> 3;
    const int b_row = ((b_mi >> 1) << 3) + (lane & 7);
    const int b_seg = b_mi & 1;

    for (int c = 0; c < NCHUNK; ++c) {
        const int s = c & 3;
        if (c < NCHUNK - 2)       asm volatile("cp.async.wait_group 2;" ::: "memory");
        else if (c == NCHUNK - 2) asm volatile("cp.async.wait_group 1;" ::: "memory");
        else                      asm volatile("cp.async.wait_group 0;" ::: "memory");
        __syncthreads();

        // issue next load first (targets a different stage than we compute)
        if (c + 3 < NCHUNK) load_chunk(c + 3, (c + 3) & 3);

        const uint32_t stage = sb + s * STAGE_BYTES;
        #pragma unroll
        for (int ks = 0; ks < 4; ++ks) {
            uint32_t a[2][4];
            #pragma unroll
            for (int mt = 0; mt < 2; ++mt) {
                const uint32_t off =
                    swz((wm + mt * 16 + a_row) * 128 + ks * 32 + a_seg * 16);
                ldsm4(a[mt][0], a[mt][1], a[mt][2], a[mt][3], stage + off);
            }
            uint32_t bH[8][2], bL[8][2];
            #pragma unroll
            for (int np = 0; np < 4; ++np) {
                const uint32_t off =
                    swz((wn + np * 16 + b_row) * 128 + ks * 32 + b_seg * 16);
                uint32_t t0, t1, t2, t3;
                ldsm4(t0, t1, t2, t3, stage + 16384 + off);
                bH[np * 2][0] = t0;     bH[np * 2][1] = t1;
                bH[np * 2 + 1][0] = t2; bH[np * 2 + 1][1] = t3;
                ldsm4(t0, t1, t2, t3, stage + 32768 + off);
                bL[np * 2][0] = t0;     bL[np * 2][1] = t1;
                bL[np * 2 + 1][0] = t2; bL[np * 2 + 1][1] = t3;
            }
            #pragma unroll
            for (int mt = 0; mt < 2; ++mt)
                #pragma unroll
                for (int nt = 0; nt < 8; ++nt) {
                    mma_f16(acc[mt][nt], a[mt], bH[nt]);
                    mma_f16(acc[mt][nt], a[mt], bL[nt]);
                }
        }
    }

    const int erow = lane >> 2, ecol = (lane & 3) * 2;
    #pragma unroll
    for (int nt = 0; nt < 8; ++nt) {
        const int ncol = n0 + wn + nt * 8 + ecol;
        const float2 bb = *(const float2*)(bias + ncol);
        #pragma unroll
        for (int mt = 0; mt < 2; ++mt) {
            const int row = m0 + wm + mt * 16 + erow;
            float* cp0 = C + (size_t)row * Dc + ncol;
            float* cp1 = C + (size_t)(row + 8) * Dc + ncol;
            *(float2*)cp0 = make_float2(acc[mt][nt][0] * INV_WSCALE + bb.x,
                                        acc[mt][nt][1] * INV_WSCALE + bb.y);
            *(float2*)cp1 = make_float2(acc[mt][nt][2] * INV_WSCALE + bb.x,
                                        acc[mt][nt][3] * INV_WSCALE + bb.y);
        }
    }
}

// ------------------------- attention: thread-per-query ---------------------
namespace {
constexpr int QT = 128;
constexpr int RW = QT + 2 * WIN;   // 160
constexpr int APAD = 66;
constexpr int ASMEM = 2 * RW * APAD * 4;   // 84480 B
}

__global__ __launch_bounds__(128) void dil_attn2(
    const float* __restrict__ Q, const float* __restrict__ K,
    const float* __restrict__ V, __half* __restrict__ Oh)
{
    extern __shared__ float sm[];
    float* Ks = sm;                    // [RW][APAD]
    float* Vs = sm + RW * APAD;

    const int tid = threadIdx.x;
    const int q0 = blockIdx.x * QT;
    const int h  = blockIdx.y;
    const int b  = blockIdx.z;

    for (int idx = tid; idx < RW * 16; idx += 128) {
        const int r  = idx >> 4;
        const int c4 = (idx & 15) * 4;
        const int j  = q0 - WIN + r;
        float4 kv = make_float4(0.f, 0.f, 0.f, 0.f), vv = kv;
        if (j >= 0 && j < Nc) {
            const size_t off = (size_t)(b * Nc + j) * Dc + h * DHc + c4;
            kv = *(const float4*)(K + off);
            vv = *(const float4*)(V + off);
        }
        float* kp = Ks + r * APAD + c4;
        kp[0] = kv.x; kp[1] = kv.y; kp[2] = kv.z; kp[3] = kv.w;
        float* vp = Vs + r * APAD + c4;
        vp[0] = vv.x; vp[1] = vv.y; vp[2] = vv.z; vp[3] = vv.w;
    }
    __syncthreads();

    const int i = q0 + tid;
    const size_t qoff = (size_t)(b * Nc + i) * Dc + h * DHc;

    float qv[DHc];
    #pragma unroll
    for (int d4 = 0; d4 < DHc; d4 += 4) {
        float4 v = *(const float4*)(Q + qoff + d4);
        qv[d4] = v.x; qv[d4 + 1] = v.y; qv[d4 + 2] = v.z; qv[d4 + 3] = v.w;
    }

    float s[NKEYS];
    #pragma unroll
    for (int m = 0; m < NKEYS; ++m) {
        const float* kr = Ks + (tid + 2 * m) * APAD;
        float acc = 0.f;
        #pragma unroll
        for (int d = 0; d < DHc; d += 2) {
            float2 kk = *(const float2*)(kr + d);
            acc += qv[d] * kk.x + qv[d + 1] * kk.y;
        }
        const int j = i + (m - KWIN) * DIL;
        s[m] = (j >= 0 && j < Nc) ? acc * 0.125f : -1e30f;
    }

    float mx = s[0];
    #pragma unroll
    for (int m = 1; m < NKEYS; ++m) mx = fmaxf(mx, s[m]);
    float den = 0.f;
    #pragma unroll
    for (int m = 0; m < NKEYS; ++m) { s[m] = __expf(s[m] - mx); den += s[m]; }
    const float inv = 1.f / den;

    float o[DHc];
    #pragma unroll
    for (int d = 0; d < DHc; ++d) o[d] = 0.f;
    #pragma unroll
    for (int m = 0; m < NKEYS; ++m) {
        const float w = s[m];
        const float* vr = Vs + (tid + 2 * m) * APAD;
        #pragma unroll
        for (int d = 0; d < DHc; d += 2) {
            float2 vv = *(const float2*)(vr + d);
            o[d]     += w * vv.x;
            o[d + 1] += w * vv.y;
        }
    }

    __half2* hp = (__half2*)(Oh + qoff);
    #pragma unroll
    for (int d = 0; d < DHc; d += 2)
        hp[d / 2] = __floats2half2_rn(o[d] * inv, o[d + 1] * inv);
}

// --------------------------------- launch ----------------------------------
extern "C" void kernel_launch(void* const* d_in, const int* in_sizes, int n_in,
                              void* d_out, int out_size) {
    const float* x  = (const float*)d_in[0];
    const float* Wq = (const float*)d_in[1];
    const float* bq = (const float*)d_in[2];
    const float* Wk = (const float*)d_in[3];
    const float* bk = (const float*)d_in[4];
    const float* Wv = (const float*)d_in[5];
    const float* bv = (const float*)d_in[6];
    const float* Wo = (const float*)d_in[7];
    const float* bo = (const float*)d_in[8];
    float* out = (float*)d_out;

    __half *xh, *whi, *wlo, *ah;
    float *Qb, *Kb, *Vb;
    cudaGetSymbolAddress((void**)&xh, g_xh);
    cudaGetSymbolAddress((void**)&whi, g_wthi);
    cudaGetSymbolAddress((void**)&wlo, g_wtlo);
    cudaGetSymbolAddress((void**)&ah, g_ah);
    cudaGetSymbolAddress((void**)&Qb, g_Q);
    cudaGetSymbolAddress((void**)&Kb, g_K);
    cudaGetSymbolAddress((void**)&Vb, g_V);

    cudaFuncSetAttribute(gemm_mma, cudaFuncAttributeMaxDynamicSharedMemorySize,
                         SMEM_TOTAL);
    cudaFuncSetAttribute(dil_attn2, cudaFuncAttributeMaxDynamicSharedMemorySize,
                         ASMEM);

    const int n4 = Mc * Dc / 4;
    convert_h<<<n4 / 256, 256>>>((const float4*)x, xh, n4);

    TransArgs ta;
    ta.W[0] = Wq; ta.W[1] = Wk; ta.W[2] = Wv; ta.W[3] = Wo;
    for (int i = 0; i < 4; ++i) {
        ta.hi[i] = whi + (size_t)i * Dc * Dc;
        ta.lo[i] = wlo + (size_t)i * Dc * Dc;
    }
    dim3 tb(32, 8), tg(32, 32, 4);
    transpose_all<<<tg, tb>>>(ta);

    GemmArgs qkv;
    qkv.Bh[0] = whi;                       qkv.Bl[0] = wlo;
    qkv.Bh[1] = whi + 1 * (size_t)Dc * Dc; qkv.Bl[1] = wlo + 1 * (size_t)Dc * Dc;
    qkv.Bh[2] = whi + 2 * (size_t)Dc * Dc; qkv.Bl[2] = wlo + 2 * (size_t)Dc * Dc;
    qkv.bias[0] = bq; qkv.bias[1] = bk; qkv.bias[2] = bv;
    qkv.C[0] = Qb; qkv.C[1] = Kb; qkv.C[2] = Vb;
    dim3 gq(Dc / 128, Mc / 128, 3);
    gemm_mma<<<gq, 256, SMEM_TOTAL>>>(xh, qkv);

    dim3 ga(Nc / QT, Hc, Bc);   // (16, 16, 4)
    dil_attn2<<<ga, 128, ASMEM>>>(Qb, Kb, Vb, ah);

    GemmArgs og;
    og.Bh[0] = whi + 3 * (size_t)Dc * Dc; og.Bl[0] = wlo + 3 * (size_t)Dc * Dc;
    og.Bh[1] = og.Bh[0]; og.Bl[1] = og.Bl[0];
    og.Bh[2] = og.Bh[0]; og.Bl[2] = og.Bl[0];
    og.bias[0] = bo; og.bias[1] = bo; og.bias[2] = bo;
    og.C[0] = out; og.C[1] = out; og.C[2] = out;
    dim3 go(Dc / 128, Mc / 128, 1);
    gemm_mma<<<go, 256, SMEM_TOTAL>>>(ah, og);
}

// round 9
// speedup vs baseline: 6.8356x; 1.2778x over previous
#include <cuda_runtime.h>
#include <cuda_fp16.h>
#include <cstdint>

// ---------------------------------------------------------------------------
// DilatedMHCABlock round 9 (= round 6/7/8 resubmit; all three benches were
// infra GPUAcquisitionTimeouts — this source has never executed):
//  - single-term fp16 HMMA GEMM (A fp16 @ W^T fp16, fp32 accum)
//  - fp16 dataflow: QKV GEMM emits fp16; attention consumes/stages fp16
//  - attention smem 42KB (fp16, pad-66) -> ~2.5x occupancy, half DRAM traffic
// ---------------------------------------------------------------------------

namespace {
constexpr int Bc = 4, Nc = 2048, Dc = 1024, Hc = 16, DHc = 64;
constexpr int KWIN = 8, DIL = 2, WIN = KWIN * DIL;   // 16
constexpr int Mc = Bc * Nc;                          // 8192
constexpr int NKEYS = 2 * KWIN + 1;                  // 17
}

// ------------------------- device scratch (no allocs) ----------------------
__device__ __align__(1024) __half g_xh[Mc * Dc];
__device__ __align__(1024) __half g_wt[4][Dc * Dc];    // W^T fp16 [N,K]
__device__ __align__(1024) __half g_Qh[Mc * Dc];
__device__ __align__(1024) __half g_Kh[Mc * Dc];
__device__ __align__(1024) __half g_Vh[Mc * Dc];
__device__ __align__(1024) __half g_ah[Mc * Dc];

// ------------------------------ helpers ------------------------------------
__device__ __forceinline__ uint32_t s2u(const void* p) {
    uint32_t a;
    asm("{ .reg .u64 t; cvta.to.shared.u64 t, %1; cvt.u32.u64 %0, t; }"
        : "=r"(a) : "l"(p));
    return a;
}
__device__ __forceinline__ uint32_t swz(uint32_t o) {   // SW128 xor swizzle
    return o ^ ((o >> 3) & 0x70);
}
__device__ __forceinline__ void ldsm4(uint32_t& r0, uint32_t& r1, uint32_t& r2,
                                      uint32_t& r3, uint32_t addr) {
    asm volatile("ldmatrix.sync.aligned.m8n8.x4.shared.b16 {%0,%1,%2,%3}, [%4];"
                 : "=r"(r0), "=r"(r1), "=r"(r2), "=r"(r3) : "r"(addr));
}
__device__ __forceinline__ void mma_f16(float* d, const uint32_t* a,
                                        const uint32_t* b) {
    asm volatile(
        "mma.sync.aligned.m16n8k16.row.col.f32.f16.f16.f32 "
        "{%0,%1,%2,%3}, {%4,%5,%6,%7}, {%8,%9}, {%0,%1,%2,%3};"
        : "+f"(d[0]), "+f"(d[1]), "+f"(d[2]), "+f"(d[3])
        : "r"(a[0]), "r"(a[1]), "r"(a[2]), "r"(a[3]), "r"(b[0]), "r"(b[1]));
}

// ------------------------- conversion kernels ------------------------------
__global__ __launch_bounds__(256) void convert_h(
    const float4* __restrict__ in, __half* __restrict__ out, int n4)
{
    int i = blockIdx.x * blockDim.x + threadIdx.x;
    if (i >= n4) return;
    float4 v = in[i];
    __half2* op = (__half2*)out;
    op[i * 2]     = __floats2half2_rn(v.x, v.y);
    op[i * 2 + 1] = __floats2half2_rn(v.z, v.w);
}

// all 4 weights: W [K,N] fp32 -> W^T [N,K] fp16
struct TransArgs {
    const float* W[4];
    __half* T[4];
};

__global__ __launch_bounds__(256) void transpose_all(TransArgs args)
{
    __shared__ float t[32][33];
    const int tx = threadIdx.x, ty = threadIdx.y;   // (32, 8)
    const int bx = blockIdx.x, by = blockIdx.y, z = blockIdx.z;
    const float* __restrict__ W = args.W[z];
    __half* __restrict__ T = args.T[z];
    #pragma unroll
    for (int i = 0; i < 4; ++i)
        t[ty + 8 * i][tx] = W[(by * 32 + ty + 8 * i) * Dc + bx * 32 + tx];
    __syncthreads();
    #pragma unroll
    for (int i = 0; i < 4; ++i) {
        int n = bx * 32 + ty + 8 * i, kk = by * 32 + tx;
        T[n * Dc + kk] = __float2half_rn(t[tx][ty + 8 * i]);
    }
}

// ------------------------- mma.sync single-term GEMM -----------------------
namespace {
constexpr int STAGES = 4;
constexpr int STAGE_BYTES = 32768;     // A | B, 16KB each
constexpr int SMEM_TOTAL = STAGES * STAGE_BYTES;   // 128 KB
constexpr int NCHUNK = Dc / 64;        // 16
}

template <typename OutT> struct GArgs {
    const __half* Bt[3];
    const float* bias[3];
    OutT* C[3];
};

template <typename OutT>
__global__ __launch_bounds__(256) void gemm_mma(
    const __half* __restrict__ Ah, GArgs<OutT> args)
{
    extern __shared__ char smem[];
    const uint32_t sb = s2u(smem);
    const int tid = threadIdx.x, wid = tid >> 5, lane = tid & 31;
    const int m0 = blockIdx.y * 128, n0 = blockIdx.x * 128;
    const int z = blockIdx.z;
    const __half* __restrict__ Bt = args.Bt[z];
    const float* __restrict__ bias = args.bias[z];
    OutT* __restrict__ C = args.C[z];

    const int wm = (wid & 3) * 32;      // warp m offset
    const int wn = (wid >> 2) * 64;     // warp n offset

    const int col = tid & 7;            // 16B unit within 128B row
    const int r0  = tid >> 3;           // 0..31

    auto load_chunk = [&](int c, int s) {
        const uint32_t base = sb + s * STAGE_BYTES;
        #pragma unroll
        for (int i = 0; i < 4; ++i) {
            const int r = r0 + i * 32;
            const uint32_t so = swz(r * 128 + col * 16);
            const size_t ga = (size_t)(m0 + r) * Dc + c * 64 + col * 8;
            const size_t gb = (size_t)(n0 + r) * Dc + c * 64 + col * 8;
            asm volatile("cp.async.cg.shared.global [%0], [%1], 16;"
                         :: "r"(base + so), "l"(Ah + ga) : "memory");
            asm volatile("cp.async.cg.shared.global [%0], [%1], 16;"
                         :: "r"(base + 16384 + so), "l"(Bt + gb) : "memory");
        }
        asm volatile("cp.async.commit_group;" ::: "memory");
    };

    float acc[2][8][4];
    #pragma unroll
    for (int mt = 0; mt < 2; ++mt)
        #pragma unroll
        for (int nt = 0; nt < 8; ++nt)
            #pragma unroll
            for (int j = 0; j < 4; ++j) acc[mt][nt][j] = 0.f;

    load_chunk(0, 0);
    load_chunk(1, 1);
    load_chunk(2, 2);

    const int a_row = lane & 15;
    const int a_seg = lane >> 4;
    const int b_mi  = lane >> 3;
    const int b_row = ((b_mi >> 1) << 3) + (lane & 7);
    const int b_seg = b_mi & 1;

    for (int c = 0; c < NCHUNK; ++c) {
        const int s = c & 3;
        if (c < NCHUNK - 2)       asm volatile("cp.async.wait_group 2;" ::: "memory");
        else if (c == NCHUNK - 2) asm volatile("cp.async.wait_group 1;" ::: "memory");
        else                      asm volatile("cp.async.wait_group 0;" ::: "memory");
        __syncthreads();

        if (c + 3 < NCHUNK) load_chunk(c + 3, (c + 3) & 3);

        const uint32_t stage = sb + s * STAGE_BYTES;
        #pragma unroll
        for (int ks = 0; ks < 4; ++ks) {
            uint32_t a[2][4];
            #pragma unroll
            for (int mt = 0; mt < 2; ++mt) {
                const uint32_t off =
                    swz((wm + mt * 16 + a_row) * 128 + ks * 32 + a_seg * 16);
                ldsm4(a[mt][0], a[mt][1], a[mt][2], a[mt][3], stage + off);
            }
            uint32_t b[8][2];
            #pragma unroll
            for (int np = 0; np < 4; ++np) {
                const uint32_t off =
                    swz((wn + np * 16 + b_row) * 128 + ks * 32 + b_seg * 16);
                uint32_t t0, t1, t2, t3;
                ldsm4(t0, t1, t2, t3, stage + 16384 + off);
                b[np * 2][0] = t0;     b[np * 2][1] = t1;
                b[np * 2 + 1][0] = t2; b[np * 2 + 1][1] = t3;
            }
            #pragma unroll
            for (int mt = 0; mt < 2; ++mt)
                #pragma unroll
                for (int nt = 0; nt < 8; ++nt)
                    mma_f16(acc[mt][nt], a[mt], b[nt]);
        }
    }

    const int erow = lane >> 2, ecol = (lane & 3) * 2;
    #pragma unroll
    for (int nt = 0; nt < 8; ++nt) {
        const int ncol = n0 + wn + nt * 8 + ecol;
        const float2 bb = *(const float2*)(bias + ncol);
        #pragma unroll
        for (int mt = 0; mt < 2; ++mt) {
            const int row = m0 + wm + mt * 16 + erow;
            float v00 = acc[mt][nt][0] + bb.x, v01 = acc[mt][nt][1] + bb.y;
            float v10 = acc[mt][nt][2] + bb.x, v11 = acc[mt][nt][3] + bb.y;
            if constexpr (sizeof(OutT) == 2) {
                *(__half2*)((__half*)C + (size_t)row * Dc + ncol) =
                    __floats2half2_rn(v00, v01);
                *(__half2*)((__half*)C + (size_t)(row + 8) * Dc + ncol) =
                    __floats2half2_rn(v10, v11);
            } else {
                *(float2*)((float*)C + (size_t)row * Dc + ncol) =
                    make_float2(v00, v01);
                *(float2*)((float*)C + (size_t)(row + 8) * Dc + ncol) =
                    make_float2(v10, v11);
            }
        }
    }
}

// ------------------------- attention (fp16 in/out) -------------------------
namespace {
constexpr int QT = 128;
constexpr int RW = QT + 2 * WIN;   // 160
constexpr int APAD = 66;           // halves; 132B stride = 33 words, conflict-free
constexpr int ASMEM = 2 * RW * APAD * 2;   // 42240 B
}

__global__ __launch_bounds__(128) void dil_attn3(
    const __half* __restrict__ Q, const __half* __restrict__ K,
    const __half* __restrict__ V, __half* __restrict__ Oh)
{
    extern __shared__ __half smh[];
    __half* Ks = smh;                  // [RW][APAD]
    __half* Vs = smh + RW * APAD;

    const int tid = threadIdx.x;
    const int q0 = blockIdx.x * QT;
    const int h  = blockIdx.y;
    const int b  = blockIdx.z;

    // stage K/V rows [q0-16, q0+144): 8 halves (16B) per thread-iter
    for (int idx = tid; idx < RW * 8; idx += 128) {
        const int r  = idx >> 3;
        const int c8 = (idx & 7) * 8;
        const int j  = q0 - WIN + r;
        uint4 kv = make_uint4(0u, 0u, 0u, 0u), vv = kv;
        if (j >= 0 && j < Nc) {
            const size_t off = (size_t)(b * Nc + j) * Dc + h * DHc + c8;
            kv = *(const uint4*)(K + off);
            vv = *(const uint4*)(V + off);
        }
        uint32_t* kp = (uint32_t*)(Ks + r * APAD + c8);
        kp[0] = kv.x; kp[1] = kv.y; kp[2] = kv.z; kp[3] = kv.w;
        uint32_t* vp = (uint32_t*)(Vs + r * APAD + c8);
        vp[0] = vv.x; vp[1] = vv.y; vp[2] = vv.z; vp[3] = vv.w;
    }
    __syncthreads();

    const int i = q0 + tid;
    const size_t qoff = (size_t)(b * Nc + i) * Dc + h * DHc;

    float qv[DHc];
    #pragma unroll
    for (int d2 = 0; d2 < DHc; d2 += 2) {
        float2 v = __half22float2(*(const __half2*)(Q + qoff + d2));
        qv[d2] = v.x; qv[d2 + 1] = v.y;
    }

    float s[NKEYS];
    #pragma unroll
    for (int m = 0; m < NKEYS; ++m) {
        const __half* kr = Ks + (tid + 2 * m) * APAD;
        float acc = 0.f;
        #pragma unroll
        for (int d = 0; d < DHc; d += 2) {
            float2 kk = __half22float2(*(const __half2*)(kr + d));
            acc += qv[d] * kk.x + qv[d + 1] * kk.y;
        }
        const int j = i + (m - KWIN) * DIL;
        s[m] = (j >= 0 && j < Nc) ? acc * 0.125f : -1e30f;
    }

    float mx = s[0];
    #pragma unroll
    for (int m = 1; m < NKEYS; ++m) mx = fmaxf(mx, s[m]);
    float den = 0.f;
    #pragma unroll
    for (int m = 0; m < NKEYS; ++m) { s[m] = __expf(s[m] - mx); den += s[m]; }
    const float inv = 1.f / den;

    float o[DHc];
    #pragma unroll
    for (int d = 0; d < DHc; ++d) o[d] = 0.f;
    #pragma unroll
    for (int m = 0; m < NKEYS; ++m) {
        const float w = s[m];
        const __half* vr = Vs + (tid + 2 * m) * APAD;
        #pragma unroll
        for (int d = 0; d < DHc; d += 2) {
            float2 vv = __half22float2(*(const __half2*)(vr + d));
            o[d]     += w * vv.x;
            o[d + 1] += w * vv.y;
        }
    }

    __half2* hp = (__half2*)(Oh + qoff);
    #pragma unroll
    for (int d = 0; d < DHc; d += 2)
        hp[d / 2] = __floats2half2_rn(o[d] * inv, o[d + 1] * inv);
}

// --------------------------------- launch ----------------------------------
extern "C" void kernel_launch(void* const* d_in, const int* in_sizes, int n_in,
                              void* d_out, int out_size) {
    const float* x  = (const float*)d_in[0];
    const float* Wq = (const float*)d_in[1];
    const float* bq = (const float*)d_in[2];
    const float* Wk = (const float*)d_in[3];
    const float* bk = (const float*)d_in[4];
    const float* Wv = (const float*)d_in[5];
    const float* bv = (const float*)d_in[6];
    const float* Wo = (const float*)d_in[7];
    const float* bo = (const float*)d_in[8];
    float* out = (float*)d_out;

    __half *xh, *wt, *Qh, *Kh, *Vh, *ah;
    cudaGetSymbolAddress((void**)&xh, g_xh);
    cudaGetSymbolAddress((void**)&wt, g_wt);
    cudaGetSymbolAddress((void**)&Qh, g_Qh);
    cudaGetSymbolAddress((void**)&Kh, g_Kh);
    cudaGetSymbolAddress((void**)&Vh, g_Vh);
    cudaGetSymbolAddress((void**)&ah, g_ah);

    cudaFuncSetAttribute(gemm_mma<__half>,
                         cudaFuncAttributeMaxDynamicSharedMemorySize, SMEM_TOTAL);
    cudaFuncSetAttribute(gemm_mma<float>,
                         cudaFuncAttributeMaxDynamicSharedMemorySize, SMEM_TOTAL);
    cudaFuncSetAttribute(dil_attn3,
                         cudaFuncAttributeMaxDynamicSharedMemorySize, ASMEM);

    const int n4 = Mc * Dc / 4;
    convert_h<<<n4 / 256, 256>>>((const float4*)x, xh, n4);

    TransArgs ta;
    ta.W[0] = Wq; ta.W[1] = Wk; ta.W[2] = Wv; ta.W[3] = Wo;
    for (int i = 0; i < 4; ++i) ta.T[i] = wt + (size_t)i * Dc * Dc;
    dim3 tb(32, 8), tg(32, 32, 4);
    transpose_all<<<tg, tb>>>(ta);

    GArgs<__half> qkv;
    qkv.Bt[0] = wt;
    qkv.Bt[1] = wt + 1 * (size_t)Dc * Dc;
    qkv.Bt[2] = wt + 2 * (size_t)Dc * Dc;
    qkv.bias[0] = bq; qkv.bias[1] = bk; qkv.bias[2] = bv;
    qkv.C[0] = Qh; qkv.C[1] = Kh; qkv.C[2] = Vh;
    dim3 gq(Dc / 128, Mc / 128, 3);
    gemm_mma<__half><<<gq, 256, SMEM_TOTAL>>>(xh, qkv);

    dim3 ga(Nc / QT, Hc, Bc);   // (16, 16, 4)
    dil_attn3<<<ga, 128, ASMEM>>>(Qh, Kh, Vh, ah);

    GArgs<float> og;
    og.Bt[0] = wt + 3 * (size_t)Dc * Dc;
    og.Bt[1] = og.Bt[0]; og.Bt[2] = og.Bt[0];
    og.bias[0] = bo; og.bias[1] = bo; og.bias[2] = bo;
    og.C[0] = out; og.C[1] = out; og.C[2] = out;
    dim3 go(Dc / 128, Mc / 128, 1);
    gemm_mma<float><<<go, 256, SMEM_TOTAL>>>(ah, og);
}

// round 15
// speedup vs baseline: 8.8460x; 1.2941x over previous
#include <cuda_runtime.h>
#include <cuda_fp16.h>
#include <cstdint>

// ---------------------------------------------------------------------------
// DilatedMHCABlock round 15 (= round 10-14 resubmit; five consecutive infra
// GPUAcquisitionTimeouts — the 4-thread/query attention has never executed):
//  - GEMM unchanged (single-term fp16 HMMA @ mma.sync ceiling, ~240us)
//  - attention: 4 threads per query x 16 dims each
//    -> ~70 regs (was 255, spilling), occ 12% -> ~37%, shfl_xor pair-reduce
// ---------------------------------------------------------------------------

namespace {
constexpr int Bc = 4, Nc = 2048, Dc = 1024, Hc = 16, DHc = 64;
constexpr int KWIN = 8, DIL = 2, WIN = KWIN * DIL;   // 16
constexpr int Mc = Bc * Nc;                          // 8192
constexpr int NKEYS = 2 * KWIN + 1;                  // 17
}

// ------------------------- device scratch (no allocs) ----------------------
__device__ __align__(1024) __half g_xh[Mc * Dc];
__device__ __align__(1024) __half g_wt[4][Dc * Dc];    // W^T fp16 [N,K]
__device__ __align__(1024) __half g_Qh[Mc * Dc];
__device__ __align__(1024) __half g_Kh[Mc * Dc];
__device__ __align__(1024) __half g_Vh[Mc * Dc];
__device__ __align__(1024) __half g_ah[Mc * Dc];

// ------------------------------ helpers ------------------------------------
__device__ __forceinline__ uint32_t s2u(const void* p) {
    uint32_t a;
    asm("{ .reg .u64 t; cvta.to.shared.u64 t, %1; cvt.u32.u64 %0, t; }"
        : "=r"(a) : "l"(p));
    return a;
}
__device__ __forceinline__ uint32_t swz(uint32_t o) {   // SW128 xor swizzle
    return o ^ ((o >> 3) & 0x70);
}
__device__ __forceinline__ void ldsm4(uint32_t& r0, uint32_t& r1, uint32_t& r2,
                                      uint32_t& r3, uint32_t addr) {
    asm volatile("ldmatrix.sync.aligned.m8n8.x4.shared.b16 {%0,%1,%2,%3}, [%4];"
                 : "=r"(r0), "=r"(r1), "=r"(r2), "=r"(r3) : "r"(addr));
}
__device__ __forceinline__ void mma_f16(float* d, const uint32_t* a,
                                        const uint32_t* b) {
    asm volatile(
        "mma.sync.aligned.m16n8k16.row.col.f32.f16.f16.f32 "
        "{%0,%1,%2,%3}, {%4,%5,%6,%7}, {%8,%9}, {%0,%1,%2,%3};"
        : "+f"(d[0]), "+f"(d[1]), "+f"(d[2]), "+f"(d[3])
        : "r"(a[0]), "r"(a[1]), "r"(a[2]), "r"(a[3]), "r"(b[0]), "r"(b[1]));
}

// ------------------------- conversion kernels ------------------------------
__global__ __launch_bounds__(256) void convert_h(
    const float4* __restrict__ in, __half* __restrict__ out, int n4)
{
    int i = blockIdx.x * blockDim.x + threadIdx.x;
    if (i >= n4) return;
    float4 v = in[i];
    __half2* op = (__half2*)out;
    op[i * 2]     = __floats2half2_rn(v.x, v.y);
    op[i * 2 + 1] = __floats2half2_rn(v.z, v.w);
}

// all 4 weights: W [K,N] fp32 -> W^T [N,K] fp16
struct TransArgs {
    const float* W[4];
    __half* T[4];
};

__global__ __launch_bounds__(256) void transpose_all(TransArgs args)
{
    __shared__ float t[32][33];
    const int tx = threadIdx.x, ty = threadIdx.y;   // (32, 8)
    const int bx = blockIdx.x, by = blockIdx.y, z = blockIdx.z;
    const float* __restrict__ W = args.W[z];
    __half* __restrict__ T = args.T[z];
    #pragma unroll
    for (int i = 0; i < 4; ++i)
        t[ty + 8 * i][tx] = W[(by * 32 + ty + 8 * i) * Dc + bx * 32 + tx];
    __syncthreads();
    #pragma unroll
    for (int i = 0; i < 4; ++i) {
        int n = bx * 32 + ty + 8 * i, kk = by * 32 + tx;
        T[n * Dc + kk] = __float2half_rn(t[tx][ty + 8 * i]);
    }
}

// ------------------------- mma.sync single-term GEMM -----------------------
namespace {
constexpr int STAGES = 4;
constexpr int STAGE_BYTES = 32768;     // A | B, 16KB each
constexpr int SMEM_TOTAL = STAGES * STAGE_BYTES;   // 128 KB
constexpr int NCHUNK = Dc / 64;        // 16
}

template <typename OutT> struct GArgs {
    const __half* Bt[3];
    const float* bias[3];
    OutT* C[3];
};

template <typename OutT>
__global__ __launch_bounds__(256) void gemm_mma(
    const __half* __restrict__ Ah, GArgs<OutT> args)
{
    extern __shared__ char smem[];
    const uint32_t sb = s2u(smem);
    const int tid = threadIdx.x, wid = tid >> 5, lane = tid & 31;
    const int m0 = blockIdx.y * 128, n0 = blockIdx.x * 128;
    const int z = blockIdx.z;
    const __half* __restrict__ Bt = args.Bt[z];
    const float* __restrict__ bias = args.bias[z];
    OutT* __restrict__ C = args.C[z];

    const int wm = (wid & 3) * 32;      // warp m offset
    const int wn = (wid >> 2) * 64;     // warp n offset

    const int col = tid & 7;            // 16B unit within 128B row
    const int r0  = tid >> 3;           // 0..31

    auto load_chunk = [&](int c, int s) {
        const uint32_t base = sb + s * STAGE_BYTES;
        #pragma unroll
        for (int i = 0; i < 4; ++i) {
            const int r = r0 + i * 32;
            const uint32_t so = swz(r * 128 + col * 16);
            const size_t ga = (size_t)(m0 + r) * Dc + c * 64 + col * 8;
            const size_t gb = (size_t)(n0 + r) * Dc + c * 64 + col * 8;
            asm volatile("cp.async.cg.shared.global [%0], [%1], 16;"
                         :: "r"(base + so), "l"(Ah + ga) : "memory");
            asm volatile("cp.async.cg.shared.global [%0], [%1], 16;"
                         :: "r"(base + 16384 + so), "l"(Bt + gb) : "memory");
        }
        asm volatile("cp.async.commit_group;" ::: "memory");
    };

    float acc[2][8][4];
    #pragma unroll
    for (int mt = 0; mt < 2; ++mt)
        #pragma unroll
        for (int nt = 0; nt < 8; ++nt)
            #pragma unroll
            for (int j = 0; j < 4; ++j) acc[mt][nt][j] = 0.f;

    load_chunk(0, 0);
    load_chunk(1, 1);
    load_chunk(2, 2);

    const int a_row = lane & 15;
    const int a_seg = lane >> 4;
    const int b_mi  = lane >> 3;
    const int b_row = ((b_mi >> 1) << 3) + (lane & 7);
    const int b_seg = b_mi & 1;

    for (int c = 0; c < NCHUNK; ++c) {
        const int s = c & 3;
        if (c < NCHUNK - 2)       asm volatile("cp.async.wait_group 2;" ::: "memory");
        else if (c == NCHUNK - 2) asm volatile("cp.async.wait_group 1;" ::: "memory");
        else                      asm volatile("cp.async.wait_group 0;" ::: "memory");
        __syncthreads();

        if (c + 3 < NCHUNK) load_chunk(c + 3, (c + 3) & 3);

        const uint32_t stage = sb + s * STAGE_BYTES;
        #pragma unroll
        for (int ks = 0; ks < 4; ++ks) {
            uint32_t a[2][4];
            #pragma unroll
            for (int mt = 0; mt < 2; ++mt) {
                const uint32_t off =
                    swz((wm + mt * 16 + a_row) * 128 + ks * 32 + a_seg * 16);
                ldsm4(a[mt][0], a[mt][1], a[mt][2], a[mt][3], stage + off);
            }
            uint32_t b[8][2];
            #pragma unroll
            for (int np = 0; np < 4; ++np) {
                const uint32_t off =
                    swz((wn + np * 16 + b_row) * 128 + ks * 32 + b_seg * 16);
                uint32_t t0, t1, t2, t3;
                ldsm4(t0, t1, t2, t3, stage + 16384 + off);
                b[np * 2][0] = t0;     b[np * 2][1] = t1;
                b[np * 2 + 1][0] = t2; b[np * 2 + 1][1] = t3;
            }
            #pragma unroll
            for (int mt = 0; mt < 2; ++mt)
                #pragma unroll
                for (int nt = 0; nt < 8; ++nt)
                    mma_f16(acc[mt][nt], a[mt], b[nt]);
        }
    }

    const int erow = lane >> 2, ecol = (lane & 3) * 2;
    #pragma unroll
    for (int nt = 0; nt < 8; ++nt) {
        const int ncol = n0 + wn + nt * 8 + ecol;
        const float2 bb = *(const float2*)(bias + ncol);
        #pragma unroll
        for (int mt = 0; mt < 2; ++mt) {
            const int row = m0 + wm + mt * 16 + erow;
            float v00 = acc[mt][nt][0] + bb.x, v01 = acc[mt][nt][1] + bb.y;
            float v10 = acc[mt][nt][2] + bb.x, v11 = acc[mt][nt][3] + bb.y;
            if constexpr (sizeof(OutT) == 2) {
                *(__half2*)((__half*)C + (size_t)row * Dc + ncol) =
                    __floats2half2_rn(v00, v01);
                *(__half2*)((__half*)C + (size_t)(row + 8) * Dc + ncol) =
                    __floats2half2_rn(v10, v11);
            } else {
                *(float2*)((float*)C + (size_t)row * Dc + ncol) =
                    make_float2(v00, v01);
                *(float2*)((float*)C + (size_t)(row + 8) * Dc + ncol) =
                    make_float2(v10, v11);
            }
        }
    }
}

// ------------------- attention: 4 threads/query x 16 dims ------------------
// Block = 256 threads = 64 queries x 4 parts. K/V window (96 rows x 64) fp16
// in smem, stride 66 halves. Score = partial dot + 2x shfl_xor. Softmax
// duplicated across the 4 lanes of a query (cheap, avoids divergence).
namespace {
constexpr int QT4 = 64;                 // queries per block
constexpr int RW4 = QT4 + 2 * WIN;      // 96 rows
constexpr int APAD = 66;                // halves; bank = q + 8*part + d/2 (unique)
}

__global__ __launch_bounds__(256, 3) void dil_attn4(
    const __half* __restrict__ Q, const __half* __restrict__ K,
    const __half* __restrict__ V, __half* __restrict__ Oh)
{
    __shared__ __half Ks[RW4 * APAD];
    __shared__ __half Vs[RW4 * APAD];

    const int tid = threadIdx.x;
    const int q0 = blockIdx.x * QT4;
    const int h  = blockIdx.y;
    const int b  = blockIdx.z;

    // stage K/V rows [q0-16, q0+80): 96 rows x 8 uint4-chunks
    for (int idx = tid; idx < RW4 * 8; idx += 256) {
        const int r  = idx >> 3;
        const int c8 = (idx & 7) * 8;
        const int j  = q0 - WIN + r;
        uint4 kv = make_uint4(0u, 0u, 0u, 0u), vv = kv;
        if (j >= 0 && j < Nc) {
            const size_t off = (size_t)(b * Nc + j) * Dc + h * DHc + c8;
            kv = *(const uint4*)(K + off);
            vv = *(const uint4*)(V + off);
        }
        uint32_t* kp = (uint32_t*)(Ks + r * APAD + c8);
        kp[0] = kv.x; kp[1] = kv.y; kp[2] = kv.z; kp[3] = kv.w;
        uint32_t* vp = (uint32_t*)(Vs + r * APAD + c8);
        vp[0] = vv.x; vp[1] = vv.y; vp[2] = vv.z; vp[3] = vv.w;
    }
    __syncthreads();

    const int ql   = tid >> 2;          // 0..63 local query
    const int part = tid & 3;           // 16-dim slice
    const int i = q0 + ql;
    const size_t qoff = (size_t)(b * Nc + i) * Dc + h * DHc + part * 16;

    float qv[16];
    #pragma unroll
    for (int d2 = 0; d2 < 16; d2 += 2) {
        float2 v = __half22float2(*(const __half2*)(Q + qoff + d2));
        qv[d2] = v.x; qv[d2 + 1] = v.y;
    }

    float s[NKEYS];
    #pragma unroll
    for (int m = 0; m < NKEYS; ++m) {
        const __half* kr = Ks + (ql + 2 * m) * APAD + part * 16;
        float acc = 0.f;
        #pragma unroll
        for (int d = 0; d < 16; d += 2) {
            float2 kk = __half22float2(*(const __half2*)(kr + d));
            acc += qv[d] * kk.x + qv[d + 1] * kk.y;
        }
        // combine 4 partials (lanes of one query are adjacent: xor 1, xor 2)
        acc += __shfl_xor_sync(0xffffffffu, acc, 1);
        acc += __shfl_xor_sync(0xffffffffu, acc, 2);
        const int j = i + (m - KWIN) * DIL;
        s[m] = (j >= 0 && j < Nc) ? acc * 0.125f : -1e30f;
    }

    float mx = s[0];
    #pragma unroll
    for (int m = 1; m < NKEYS; ++m) mx = fmaxf(mx, s[m]);
    float den = 0.f;
    #pragma unroll
    for (int m = 0; m < NKEYS; ++m) { s[m] = __expf(s[m] - mx); den += s[m]; }
    const float inv = 1.f / den;

    float o[16];
    #pragma unroll
    for (int d = 0; d < 16; ++d) o[d] = 0.f;
    #pragma unroll
    for (int m = 0; m < NKEYS; ++m) {
        const float w = s[m];
        const __half* vr = Vs + (ql + 2 * m) * APAD + part * 16;
        #pragma unroll
        for (int d = 0; d < 16; d += 2) {
            float2 vv = __half22float2(*(const __half2*)(vr + d));
            o[d]     += w * vv.x;
            o[d + 1] += w * vv.y;
        }
    }

    __half2* hp = (__half2*)(Oh + qoff);
    #pragma unroll
    for (int d = 0; d < 16; d += 2)
        hp[d / 2] = __floats2half2_rn(o[d] * inv, o[d + 1] * inv);
}

// --------------------------------- launch ----------------------------------
extern "C" void kernel_launch(void* const* d_in, const int* in_sizes, int n_in,
                              void* d_out, int out_size) {
    const float* x  = (const float*)d_in[0];
    const float* Wq = (const float*)d_in[1];
    const float* bq = (const float*)d_in[2];
    const float* Wk = (const float*)d_in[3];
    const float* bk = (const float*)d_in[4];
    const float* Wv = (const float*)d_in[5];
    const float* bv = (const float*)d_in[6];
    const float* Wo = (const float*)d_in[7];
    const float* bo = (const float*)d_in[8];
    float* out = (float*)d_out;

    __half *xh, *wt, *Qh, *Kh, *Vh, *ah;
    cudaGetSymbolAddress((void**)&xh, g_xh);
    cudaGetSymbolAddress((void**)&wt, g_wt);
    cudaGetSymbolAddress((void**)&Qh, g_Qh);
    cudaGetSymbolAddress((void**)&Kh, g_Kh);
    cudaGetSymbolAddress((void**)&Vh, g_Vh);
    cudaGetSymbolAddress((void**)&ah, g_ah);

    cudaFuncSetAttribute(gemm_mma<__half>,
                         cudaFuncAttributeMaxDynamicSharedMemorySize, SMEM_TOTAL);
    cudaFuncSetAttribute(gemm_mma<float>,
                         cudaFuncAttributeMaxDynamicSharedMemorySize, SMEM_TOTAL);

    const int n4 = Mc * Dc / 4;
    convert_h<<<n4 / 256, 256>>>((const float4*)x, xh, n4);

    TransArgs ta;
    ta.W[0] = Wq; ta.W[1] = Wk; ta.W[2] = Wv; ta.W[3] = Wo;
    for (int i = 0; i < 4; ++i) ta.T[i] = wt + (size_t)i * Dc * Dc;
    dim3 tb(32, 8), tg(32, 32, 4);
    transpose_all<<<tg, tb>>>(ta);

    GArgs<__half> qkv;
    qkv.Bt[0] = wt;
    qkv.Bt[1] = wt + 1 * (size_t)Dc * Dc;
    qkv.Bt[2] = wt + 2 * (size_t)Dc * Dc;
    qkv.bias[0] = bq; qkv.bias[1] = bk; qkv.bias[2] = bv;
    qkv.C[0] = Qh; qkv.C[1] = Kh; qkv.C[2] = Vh;
    dim3 gq(Dc / 128, Mc / 128, 3);
    gemm_mma<__half><<<gq, 256, SMEM_TOTAL>>>(xh, qkv);

    dim3 ga(Nc / QT4, Hc, Bc);   // (32, 16, 4)
    dil_attn4<<<ga, 256>>>(Qh, Kh, Vh, ah);

    GArgs<float> og;
    og.Bt[0] = wt + 3 * (size_t)Dc * Dc;
    og.Bt[1] = og.Bt[0]; og.Bt[2] = og.Bt[0];
    og.bias[0] = bo; og.bias[1] = bo; og.bias[2] = bo;
    og.C[0] = out; og.C[1] = out; og.C[2] = out;
    dim3 go(Dc / 128, Mc / 128, 1);
    gemm_mma<float><<<go, 256, SMEM_TOTAL>>>(ah, og);
}